// round 15
// baseline (speedup 1.0000x reference)
#include <cuda_runtime.h>
#include <cuda_fp16.h>
#include <math.h>

#define NB    8
#define NTOK  4096
#define DIMC  256
#define HIDC  512
#define MROWS (NB*NTOK)   // 32768

// ---------------- fp32 scratch ----------------
#define OFF_GP    0
#define OFF_MEAN  (OFF_GP   + MROWS)
#define OFF_RSTD  (OFF_MEAN + MROWS)
#define OFF_XDBL  (OFF_RSTD + MROWS)            // [MROWS,64]
#define OFF_DELTA (OFF_XDBL + MROWS*64)         // [MROWS,512]
#define OFF_S0    (OFF_DELTA+ MROWS*HIDC)
#define OFF_U0    (OFF_S0   + 512)
#define OFF_S3    (OFF_U0   + 512)
#define OFF_U3    (OFF_S3   + 256)
#define OFF_S4    (OFF_U3   + 256)
#define OFF_U4    (OFF_S4   + 512)
#define OFF_ZERO  (OFF_U4   + 512)
#define FTOTAL    (OFF_ZERO + 512)

__device__ __align__(16) float g_fbuf[FTOTAL];

// ---------------- fp16 scratch ----------------
#define HOFF_X16  0                              // [MROWS,256]
#define HOFF_XP16 (HOFF_X16 + MROWS*DIMC)        // [MROWS,512]
#define HOFF_U16  (HOFF_XP16+ MROWS*HIDC)        // [MROWS,512]
#define HOFF_XD16 (HOFF_U16 + MROWS*HIDC)        // [MROWS,64]
#define HOFF_Y16  (HOFF_XD16+ MROWS*64)          // [MROWS,512]
#define HOFF_X116 (HOFF_Y16 + MROWS*HIDC)        // [MROWS,256]
#define HOFF_H116 (HOFF_X116+ MROWS*DIMC)        // [MROWS,512]
#define HOFF_WF0  (HOFF_H116+ MROWS*HIDC)        // [512,256]
#define HOFF_WF3  (HOFF_WF0 + 512*256)           // [256,512]
#define HOFF_WF4  (HOFF_WF3 + 256*512)           // [512,256]
#define HOFF_XPW  (HOFF_WF4 + 512*256)           // [64,512]
#define HOFF_DTW  (HOFF_XPW + 64*512)            // [512,32]
#define HOFF_M2W  (HOFF_DTW + 512*32)            // [256,512]
#define HTOTAL    (HOFF_M2W + 256*512)

__device__ __align__(16) __half g_hbuf[HTOTAL];
__device__ int g_ibuf[2*MROWS + 32];             // idx, inv

// ================= PTX helpers =================
__device__ __forceinline__ void cpa16(unsigned s, const void* g){
    asm volatile("cp.async.cg.shared.global [%0], [%1], 16;" :: "r"(s), "l"(g));
}
#define CP_COMMIT() asm volatile("cp.async.commit_group;" ::: "memory")
#define CP_WAIT2()  asm volatile("cp.async.wait_group 2;" ::: "memory")
__device__ __forceinline__ unsigned smem_u32(const void* p){
    unsigned a;
    asm("{ .reg .u64 t; cvta.to.shared.u64 t, %1; cvt.u32.u64 %0, t; }" : "=r"(a) : "l"(p));
    return a;
}
__device__ __forceinline__ void mma16(float* c, const unsigned* a, const unsigned* b){
    asm volatile("mma.sync.aligned.m16n8k16.row.col.f32.f16.f16.f32 "
        "{%0,%1,%2,%3}, {%4,%5,%6,%7}, {%8,%9}, {%0,%1,%2,%3};"
        : "+f"(c[0]),"+f"(c[1]),"+f"(c[2]),"+f"(c[3])
        : "r"(a[0]),"r"(a[1]),"r"(a[2]),"r"(a[3]), "r"(b[0]),"r"(b[1]));
}
__device__ __forceinline__ void ldsm4(unsigned* r, unsigned addr){
    asm volatile("ldmatrix.sync.aligned.m8n8.x4.shared.b16 {%0,%1,%2,%3}, [%4];"
        : "=r"(r[0]),"=r"(r[1]),"=r"(r[2]),"=r"(r[3]) : "r"(addr));
}

// ---------------- merged prep: LN-fold x3, weight cvt x3, init ----------------
__device__ __forceinline__ void foldw(const float* __restrict__ W, const float* __restrict__ g,
                                      const float* __restrict__ b, const float* __restrict__ bias,
                                      __half* __restrict__ Wf, float* __restrict__ sv,
                                      float* __restrict__ uv, int n, int K, int lane){
    float s = 0.f, t = 0.f;
    for (int c=lane; c<K; c+=32){
        float w = W[(size_t)n*K + c];
        __half wh = __float2half_rn(w * g[c]);
        Wf[(size_t)n*K + c] = wh;
        s += __half2float(wh);
        t += w * b[c];
    }
    #pragma unroll
    for (int o=16;o>0;o>>=1){
        s += __shfl_down_sync(0xffffffffu, s, o);
        t += __shfl_down_sync(0xffffffffu, t, o);
    }
    if (lane == 0){ sv[n] = s; uv[n] = t + bias[n]; }
}

__global__ void k_prep(
    const float* in_w, const float* n1g, const float* n1b, const float* in_b,
    const float* outp_w, const float* ong, const float* onb, const float* outp_b,
    const float* mlp_w1, const float* n2g, const float* n2b, const float* mlp_b1,
    const float* x_proj_w, const float* dt_w, const float* mlp_w2)
{
    __half* hb = g_hbuf;
    float*  fb = g_fbuf;
    int blk = blockIdx.x, tid = threadIdx.x;
    int warp = tid >> 5, lane = tid & 31;
    if (blk == 0) fb[OFF_ZERO + tid] = 0.f;
    if (blk == 1) fb[OFF_ZERO + 256 + tid] = 0.f;

    if (blk < 64){
        foldw(in_w, n1g, n1b, in_b, hb+HOFF_WF0, fb+OFF_S0, fb+OFF_U0, blk*8+warp, 256, lane);
    } else if (blk < 96){
        foldw(outp_w, ong, onb, outp_b, hb+HOFF_WF3, fb+OFF_S3, fb+OFF_U3, (blk-64)*8+warp, 512, lane);
    } else if (blk < 160){
        foldw(mlp_w1, n2g, n2b, mlp_b1, hb+HOFF_WF4, fb+OFF_S4, fb+OFF_U4, (blk-96)*8+warp, 256, lane);
    } else {
        int t = (blk-160)*256 + tid;
        if (t < 32768)       hb[HOFF_XPW + t] = __float2half_rn(x_proj_w[t]);
        else if (t < 49152)  hb[HOFF_DTW + t - 32768] = __float2half_rn(dt_w[t - 32768]);
        else                 hb[HOFF_M2W + t - 49152] = __float2half_rn(mlp_w2[t - 49152]);
    }
}

// row stats (fp32 in); optionally writes fp16 copy
template<int KW, bool WRH>
__global__ void k_rowstats(const float* __restrict__ A, float* __restrict__ mean,
                           float* __restrict__ rstd, __half* __restrict__ o16){
    int row  = blockIdx.x*8 + (threadIdx.x >> 5);
    int lane = threadIdx.x & 31;
    const float4* p = (const float4*)(A + (size_t)row*KW);
    float s = 0.f, q = 0.f;
    #pragma unroll
    for (int c=lane; c<KW/4; c+=32){
        float4 v = p[c];
        s += v.x+v.y+v.z+v.w;
        q += v.x*v.x + v.y*v.y + v.z*v.z + v.w*v.w;
        if (WRH){
            *(__half2*)(o16 + (size_t)row*KW + 4*c)     = __floats2half2_rn(v.x, v.y);
            *(__half2*)(o16 + (size_t)row*KW + 4*c + 2) = __floats2half2_rn(v.z, v.w);
        }
    }
    #pragma unroll
    for (int o=16;o>0;o>>=1){
        s += __shfl_down_sync(0xffffffffu, s, o);
        q += __shfl_down_sync(0xffffffffu, q, o);
    }
    if (lane == 0){
        float m = s*(1.f/KW);
        float v = q*(1.f/KW) - m*m;
        mean[row] = m;
        rstd[row] = rsqrtf(v + 1e-5f);
    }
}

// row stats over fp16 rows
template<int KW>
__global__ void k_rowstats_h(const __half* __restrict__ A, float* __restrict__ mean,
                             float* __restrict__ rstd){
    int row  = blockIdx.x*8 + (threadIdx.x >> 5);
    int lane = threadIdx.x & 31;
    const __half2* p = (const __half2*)(A + (size_t)row*KW);
    float s = 0.f, q = 0.f;
    #pragma unroll
    for (int c=lane; c<KW/2; c+=32){
        float2 v = __half22float2(p[c]);
        s += v.x + v.y;
        q += v.x*v.x + v.y*v.y;
    }
    #pragma unroll
    for (int o=16;o>0;o>>=1){
        s += __shfl_down_sync(0xffffffffu, s, o);
        q += __shfl_down_sync(0xffffffffu, q, o);
    }
    if (lane == 0){
        float m = s*(1.f/KW);
        float v = q*(1.f/KW) - m*m;
        mean[row] = m;
        rstd[row] = rsqrtf(v + 1e-5f);
    }
}

// ---- fused: gradient magnitude + min/max + priority + stable bitonic argsort ----
__global__ void __launch_bounds__(1024) k_sortfused(
    const float* __restrict__ mean, const float* __restrict__ fw,
    const float* __restrict__ ps, const float* __restrict__ po,
    float* __restrict__ gp, int* __restrict__ idx, int* __restrict__ inv)
{
    __shared__ float s1[NTOK];
    __shared__ int   sv[NTOK];
    __shared__ float rmn[32], rmx[32];
    int b = blockIdx.x, tid = threadIdx.x;
    int warp = tid >> 5, lane = tid & 31;

    for (int i=tid; i<NTOK; i+=1024) s1[i] = mean[b*NTOK + i];
    float w0 = fw[0], w1 = fw[1], w2 = fw[2];
    float kk[9];
    kk[0] = -w0 - w1;        kk[1] = -2.f*w1 - w2;  kk[2] =  w0 - w1;
    kk[3] = -2.f*w0 - w2;    kk[4] =  4.f*w2;       kk[5] =  2.f*w0 - w2;
    kk[6] = -w0 + w1;        kk[7] =  2.f*w1 - w2;  kk[8] =  w0 + w1;
    __syncthreads();

    float gv[4];
    float mymin = 1e30f, mymax = 0.f;
    #pragma unroll
    for (int t=0;t<4;t++){
        int pix = tid + t*1024;
        int h = pix >> 6, w = pix & 63;
        float acc = 0.f;
        #pragma unroll
        for (int dh=-1; dh<=1; dh++)
            #pragma unroll
            for (int dw=-1; dw<=1; dw++){
                int hh = h+dh, ww = w+dw;
                float v = (hh>=0 && hh<64 && ww>=0 && ww<64) ? s1[hh*64+ww] : 0.f;
                acc += v * kk[(dh+1)*3 + (dw+1)];
            }
        float g = fabsf(acc);
        gv[t] = g;
        mymin = fminf(mymin, g); mymax = fmaxf(mymax, g);
    }
    #pragma unroll
    for (int o=16;o>0;o>>=1){
        mymin = fminf(mymin, __shfl_down_sync(0xffffffffu, mymin, o));
        mymax = fmaxf(mymax, __shfl_down_sync(0xffffffffu, mymax, o));
    }
    if (lane == 0){ rmn[warp] = mymin; rmx[warp] = mymax; }
    __syncthreads();
    if (tid < 32){
        float a = rmn[tid], c = rmx[tid];
        #pragma unroll
        for (int o=16;o>0;o>>=1){
            a = fminf(a, __shfl_down_sync(0xffffffffu, a, o));
            c = fmaxf(c, __shfl_down_sync(0xffffffffu, c, o));
        }
        if (tid == 0){ rmn[0] = a; rmx[0] = c; }
    }
    __syncthreads();
    float mn = rmn[0], mx = rmx[0];
    float psv = ps[0], pov = po[0];
    __syncthreads();
    #pragma unroll
    for (int t=0;t<4;t++){
        int pix = tid + t*1024;
        float tt = (gv[t]-mn) / (mx-mn+1e-8f);
        float z  = psv*tt + pov;
        float g  = 1.f/(1.f+expf(-z));
        gp[b*NTOK + pix] = g;
        s1[pix] = g; sv[pix] = pix;
    }
    for (int ksz=2; ksz<=NTOK; ksz<<=1){
        for (int j=ksz>>1; j>0; j>>=1){
            __syncthreads();
            #pragma unroll
            for (int base=0; base<NTOK; base+=1024){
                int i = base + tid;
                int ix = i ^ j;
                if (ix > i){
                    bool up = ((i & ksz) == 0);
                    float a = s1[i], c = s1[ix]; int va = sv[i], vc = sv[ix];
                    bool gt = (a > c) || (a == c && va > vc);
                    if (gt == up){ s1[i]=c; s1[ix]=a; sv[i]=vc; sv[ix]=va; }
                }
            }
        }
    }
    __syncthreads();
    for (int i=tid; i<NTOK; i+=1024){
        idx[b*NTOK + i]     = sv[i];
        inv[b*NTOK + sv[i]] = i;
    }
}

// ---- depthwise 3x3 CPE + sigmoid gate + permutation scatter into u16 ----
__global__ void __launch_bounds__(256) k_cpe(
    const __half* __restrict__ xp, const float* __restrict__ cw,
    const float* __restrict__ cb, const int* __restrict__ inv,
    __half* __restrict__ uo16)
{
    int h  = blockIdx.x;
    int b  = blockIdx.y;
    int ch = threadIdx.x * 2;
    float2 w[9];
    #pragma unroll
    for (int j=0;j<9;j++){ w[j].x = cw[ch*9+j]; w[j].y = cw[(ch+1)*9+j]; }
    float2 bv; bv.x = cb[ch]; bv.y = cb[ch+1];

    const __half* xpB = xp + ((size_t)b*NTOK)*HIDC + ch;
    __half* uoHB = uo16 + ((size_t)b*NTOK)*HIDC + ch;
    const int* invB = inv + b*NTOK + h*64;

    bool hm_ok = (h > 0), hp_ok = (h < 63);
    float2 zero = make_float2(0.f, 0.f);
    float2 cL[3], cM[3], cR[3];
    cL[0]=cL[1]=cL[2]=zero;
    cM[0] = hm_ok ? __half22float2(*(const __half2*)(xpB + (size_t)((h-1)*64)*HIDC)) : zero;
    cM[1] = __half22float2(*(const __half2*)(xpB + (size_t)(h*64)*HIDC));
    cM[2] = hp_ok ? __half22float2(*(const __half2*)(xpB + (size_t)((h+1)*64)*HIDC)) : zero;

    for (int ww=0; ww<64; ww++){
        if (ww < 63){
            cR[0] = hm_ok ? __half22float2(*(const __half2*)(xpB + (size_t)((h-1)*64+ww+1)*HIDC)) : zero;
            cR[1] = __half22float2(*(const __half2*)(xpB + (size_t)(h*64+ww+1)*HIDC));
            cR[2] = hp_ok ? __half22float2(*(const __half2*)(xpB + (size_t)((h+1)*64+ww+1)*HIDC)) : zero;
        } else { cR[0]=cR[1]=cR[2]=zero; }
        float ax = bv.x, ay = bv.y;
        #pragma unroll
        for (int r=0;r<3;r++){
            ax = fmaf(cL[r].x, w[r*3+0].x, ax);
            ay = fmaf(cL[r].y, w[r*3+0].y, ay);
            ax = fmaf(cM[r].x, w[r*3+1].x, ax);
            ay = fmaf(cM[r].y, w[r*3+1].y, ay);
            ax = fmaf(cR[r].x, w[r*3+2].x, ax);
            ay = fmaf(cR[r].y, w[r*3+2].y, ay);
        }
        float gx = 1.f/(1.f+__expf(-ax));
        float gy = 1.f/(1.f+__expf(-ay));
        int l = invB[ww];
        *(__half2*)(uoHB + (size_t)l*HIDC) = __floats2half2_rn(cM[1].x*gx, cM[1].y*gy);
        cL[0]=cM[0]; cL[1]=cM[1]; cL[2]=cM[2];
        cM[0]=cR[0]; cM[1]=cR[1]; cM[2]=cR[2];
    }
}

// ===== fp16 mma.sync GEMM: 256 thr / 8 warps (4x2), warp 32x64, K-chunk 32, 4-stage =====
// MODE 0: LN-folded +u -> f16 only   MODE 1: x_proj + Cm adjust (f32 + f16 copy)
// MODE 2: softplus(acc+u) (f32)      MODE 3: LN-folded, scatter + x -> f16 only
// MODE 4: LN-folded silu (f16 only)  MODE 5: acc+u+X116(f16 via C16) -> out (f32)
#define PW 20   // smem pitch in 32-bit words (40 fp16) -- stride 5 units mod 8 distinct
#define NSTG 4
template<int MODE, int NT>
__global__ void __launch_bounds__(256, 2) k_mgemm(
    const __half* __restrict__ A, int lda, int K,
    const __half* __restrict__ W,
    const float* __restrict__ rowm, const float* __restrict__ rowr,
    const float* __restrict__ svec, const float* __restrict__ uvec,
    float* __restrict__ C, __half* __restrict__ C16, int ldc,
    const float* __restrict__ aux0, const float* __restrict__ aux1,
    const float* __restrict__ aux2, const float* __restrict__ aux3,
    const int* __restrict__ ei)
{
    constexpr bool LNA  = (MODE==0 || MODE==3 || MODE==4);
    constexpr int NTILE = NT/16;
    constexpr int AW = 128*PW;
    constexpr int BW = NT*PW;
    extern __shared__ unsigned smemb[];
    unsigned sAu = smem_u32(smemb);
    unsigned sBu = sAu + NSTG*AW*4;

    int tid = threadIdx.x, lane = tid & 31, wid = tid >> 5;
    int warpM = wid & 3, warpN = wid >> 2;
    int mBase = blockIdx.y << 7;
    int nBase = blockIdx.x * NT;
    int Kt = K >> 5;
    int rA = lane >> 2, cA = lane & 3;

    float c[2][NTILE][4];
    #pragma unroll
    for (int i=0;i<2;i++)
        #pragma unroll
        for (int j=0;j<NTILE;j++)
            #pragma unroll
            for (int q=0;q<4;q++) c[i][j][q] = 0.f;

    auto ldStage = [&](int s, int k0){
        unsigned bA = sAu + s*(AW*4);
        #pragma unroll
        for (int i=tid; i<512; i+=256){
            int r = i>>2, hf = i&3;
            cpa16(bA + (r*PW + hf*4)*4, A + (size_t)(mBase+r)*lda + k0 + hf*8);
        }
        unsigned bB = sBu + s*(BW*4);
        #pragma unroll
        for (int i=tid; i<NT*4; i+=256){
            int r = i>>2, hf = i&3;
            cpa16(bB + (r*PW + hf*4)*4, W + (size_t)(nBase+r)*K + k0 + hf*8);
        }
    };

    int g8 = lane >> 3, r8 = lane & 7;
    unsigned offA[2], offB[NTILE/2];
    #pragma unroll
    for (int mt=0; mt<2; mt++){
        int row = warpM*32 + mt*16 + (g8 & 1)*8 + r8;
        offA[mt] = (unsigned)((row*PW + (g8>>1)*4)*4);
    }
    #pragma unroll
    for (int np=0; np<NTILE/2; np++){
        int row = warpN*(NT/2) + np*16 + (g8>>1)*8 + r8;
        offB[np] = (unsigned)((row*PW + (g8&1)*4)*4);
    }

    #pragma unroll
    for (int s=0; s<NSTG-1; s++){
        if (s < Kt) ldStage(s, s<<5);
        CP_COMMIT();
    }

    for (int k=0; k<Kt; k++){
        CP_WAIT2();
        __syncthreads();
        int t = k + NSTG - 1;
        if (t < Kt) ldStage(t & (NSTG-1), t<<5);
        CP_COMMIT();

        unsigned paB = sAu + (k & (NSTG-1))*(AW*4);
        unsigned pbB = sBu + (k & (NSTG-1))*(BW*4);
        #pragma unroll
        for (int kk=0; kk<2; kk++){
            unsigned koff = kk*32;
            unsigned af[2][4], bf[NTILE][2];
            ldsm4(af[0], paB + offA[0] + koff);
            ldsm4(af[1], paB + offA[1] + koff);
            #pragma unroll
            for (int np=0; np<NTILE/2; np++){
                unsigned tb[4];
                ldsm4(tb, pbB + offB[np] + koff);
                bf[2*np  ][0] = tb[0]; bf[2*np  ][1] = tb[1];
                bf[2*np+1][0] = tb[2]; bf[2*np+1][1] = tb[3];
            }
            #pragma unroll
            for (int mt=0; mt<2; mt++)
                #pragma unroll
                for (int nt=0; nt<NTILE; nt++)
                    mma16(c[mt][nt], af[mt], bf[nt]);
        }
    }

    // ---------------- epilogue ----------------
    float gcw = 0.f;
    if constexpr (MODE==1) gcw = aux3[0];

    #pragma unroll
    for (int mt=0; mt<2; mt++){
        #pragma unroll
        for (int half=0; half<2; half++){
            int m = mBase + warpM*32 + mt*16 + half*8 + rA;
            float mu = 0.f, rs = 0.f;
            if (LNA){ mu = rowm[m]; rs = rowr[m]; }
            float murs = mu*rs;
            int l = m & 4095, bb = m >> 12;
            int dest = m;
            if constexpr (MODE==3) dest = (m & ~4095) + ei[m];
            #pragma unroll
            for (int nt=0; nt<NTILE; nt++){
                int n0 = nBase + warpN*(NT/2) + nt*8 + (cA<<1);
                float vv[2] = { c[mt][nt][half*2], c[mt][nt][half*2+1] };
                float2 o;
                float* ov = (float*)&o;
                #pragma unroll
                for (int q=0; q<2; q++){
                    int n = n0 + q;
                    float acc = vv[q];
                    float v;
                    if (LNA) v = fmaf(rs, acc, fmaf(-murs, svec[n], uvec[n]));
                    else     v = acc + uvec[n];
                    if constexpr (MODE==1){
                        if (n >= 48){
                            int sidx = n - 48;
                            v += gcw * (aux0[bb*4096 + sidx*256 + (l>>4)] * aux1[l&15] + aux2[l&15]);
                        }
                    } else if constexpr (MODE==2){
                        v = fmaxf(v, 0.f) + log1pf(expf(-fabsf(v)));
                    } else if constexpr (MODE==4){
                        v = v / (1.f + expf(-v));
                    }
                    ov[q] = v;
                }
                if constexpr (MODE==3){
                    float2 xr = *(const float2*)(aux0 + (size_t)dest*ldc + n0);
                    o.x += xr.x; o.y += xr.y;
                    *(__half2*)(C16 + (size_t)dest*ldc + n0) = __floats2half2_rn(o.x, o.y);
                } else if constexpr (MODE==5){
                    float2 xr = __half22float2(*(const __half2*)(C16 + (size_t)m*ldc + n0));
                    o.x += xr.x; o.y += xr.y;
                    *(float2*)(C + (size_t)m*ldc + n0) = o;
                } else if constexpr (MODE==4 || MODE==0){
                    *(__half2*)(C16 + (size_t)m*ldc + n0) = __floats2half2_rn(o.x, o.y);
                } else if constexpr (MODE==1){
                    *(float2*)(C + (size_t)m*ldc + n0) = o;
                    *(__half2*)(C16 + (size_t)m*ldc + n0) = __floats2half2_rn(o.x, o.y);
                } else {
                    *(float2*)(C + (size_t)m*ldc + n0) = o;
                }
            }
        }
    }
}

// ------ selective scan: 8 d/warp, 4 lanes/scan, 4 states/lane, CHUNK=4 double buffer ------
#define SCHUNK 4
__global__ void __launch_bounds__(64, 8) k_scan(
    const __half* __restrict__ u16, const float* __restrict__ delta,
    const float* __restrict__ xdbl, const float* __restrict__ A_logs,
    const float* __restrict__ Ds, __half* __restrict__ y16)
{
    int lane = threadIdx.x & 31;
    int warp = threadIdx.x >> 5;      // 0..1
    int sl4  = lane & 3;
    int blk  = blockIdx.x;            // 0..255
    int b    = blk >> 5;
    int sub  = blk & 31;
    int d    = sub*16 + warp*8 + (lane >> 2);
    int p    = 4*sl4;
    float a0 = -expf(A_logs[d*16 + p    ]);
    float a1 = -expf(A_logs[d*16 + p + 1]);
    float a2 = -expf(A_logs[d*16 + p + 2]);
    float a3 = -expf(A_logs[d*16 + p + 3]);
    float dsd = Ds[d];
    size_t base = ((size_t)b*NTOK)*HIDC + d;
    size_t xb   = ((size_t)b*NTOK)*64 + 32 + p;
    float h0 = 0.f, h1 = 0.f, h2 = 0.f, h3 = 0.f;

    float  dl[2][SCHUNK], uu[2][SCHUNK];
    float4 Bv[2][SCHUNK], Cv[2][SCHUNK];

    #pragma unroll
    for (int j=0;j<SCHUNK;j++){
        dl[0][j] = delta[base + (size_t)j*HIDC];
        uu[0][j] = __half2float(u16[base + (size_t)j*HIDC]);
        Bv[0][j] = *(const float4*)(xdbl + xb + (size_t)j*64);
        Cv[0][j] = *(const float4*)(xdbl + xb + (size_t)j*64 + 16);
    }
    #pragma unroll 2
    for (int c=0; c<NTOK/SCHUNK; c++){
        int cur = c & 1, nxt = cur^1;
        if (c+1 < NTOK/SCHUNK){
            int l1 = (c+1)*SCHUNK;
            #pragma unroll
            for (int j=0;j<SCHUNK;j++){
                dl[nxt][j] = delta[base + (size_t)(l1+j)*HIDC];
                uu[nxt][j] = __half2float(u16[base + (size_t)(l1+j)*HIDC]);
                Bv[nxt][j] = *(const float4*)(xdbl + xb + (size_t)(l1+j)*64);
                Cv[nxt][j] = *(const float4*)(xdbl + xb + (size_t)(l1+j)*64 + 16);
            }
        }
        #pragma unroll
        for (int j=0;j<SCHUNK;j++){
            float dlt = dl[cur][j];
            float e0 = __expf(dlt*a0), e1 = __expf(dlt*a1);
            float e2 = __expf(dlt*a2), e3 = __expf(dlt*a3);
            float du = dlt*uu[cur][j];
            h0 = fmaf(e0, h0, du*Bv[cur][j].x);
            h1 = fmaf(e1, h1, du*Bv[cur][j].y);
            h2 = fmaf(e2, h2, du*Bv[cur][j].z);
            h3 = fmaf(e3, h3, du*Bv[cur][j].w);
            float t = fmaf(h0, Cv[cur][j].x,
                      fmaf(h1, Cv[cur][j].y,
                      fmaf(h2, Cv[cur][j].z, h3*Cv[cur][j].w)));
            t += __shfl_xor_sync(0xffffffffu, t, 1);
            t += __shfl_xor_sync(0xffffffffu, t, 2);
            if (sl4 == 0){
                float yv = fmaf(uu[cur][j], dsd, t);
                y16[base + (size_t)(c*SCHUNK+j)*HIDC] = __float2half_rn(yv);
            }
        }
    }
}

// ---------------- host launcher ----------------
extern "C" void kernel_launch(void* const* d_in, const int* in_sizes, int n_in,
                              void* d_out, int out_size) {
    const float* x        = (const float*)d_in[0];
    const float* norm1_g  = (const float*)d_in[1];
    const float* norm1_b  = (const float*)d_in[2];
    const float* fusion_w = (const float*)d_in[3];
    const float* prio_s   = (const float*)d_in[4];
    const float* prio_o   = (const float*)d_in[5];
    const float* in_w     = (const float*)d_in[6];
    const float* in_b     = (const float*)d_in[7];
    const float* cpe_w    = (const float*)d_in[8];
    const float* cpe_b    = (const float*)d_in[9];
    const float* x_proj_w = (const float*)d_in[10];
    const float* dt_w     = (const float*)d_in[11];
    const float* dt_b     = (const float*)d_in[12];
    const float* A_logs   = (const float*)d_in[13];
    const float* Ds       = (const float*)d_in[14];
    const float* gC_w     = (const float*)d_in[15];
    const float* gC_b     = (const float*)d_in[16];
    const float* gC_wt    = (const float*)d_in[17];
    const float* outn_g   = (const float*)d_in[18];
    const float* outn_b   = (const float*)d_in[19];
    const float* outp_w   = (const float*)d_in[20];
    const float* outp_b   = (const float*)d_in[21];
    const float* norm2_g  = (const float*)d_in[22];
    const float* norm2_b  = (const float*)d_in[23];
    const float* mlp_w1   = (const float*)d_in[24];
    const float* mlp_b1   = (const float*)d_in[25];
    const float* mlp_w2   = (const float*)d_in[26];
    const float* mlp_b2   = (const float*)d_in[27];
    float* out = (float*)d_out;

    float*  fb; cudaGetSymbolAddress((void**)&fb, g_fbuf);
    __half* hb; cudaGetSymbolAddress((void**)&hb, g_hbuf);
    int*    ib; cudaGetSymbolAddress((void**)&ib, g_ibuf);
    float* GP    = fb + OFF_GP;
    float* MEAN  = fb + OFF_MEAN;
    float* RSTD  = fb + OFF_RSTD;
    float* XDBL  = fb + OFF_XDBL;
    float* DELTA = fb + OFF_DELTA;
    float* S0 = fb+OFF_S0; float* U0 = fb+OFF_U0;
    float* S3 = fb+OFF_S3; float* U3 = fb+OFF_U3;
    float* S4 = fb+OFF_S4; float* U4 = fb+OFF_U4;
    float* ZV = fb+OFF_ZERO;
    __half* X16  = hb + HOFF_X16;
    __half* XP16 = hb + HOFF_XP16;
    __half* U16  = hb + HOFF_U16;
    __half* XD16 = hb + HOFF_XD16;
    __half* Y16  = hb + HOFF_Y16;
    __half* X116 = hb + HOFF_X116;
    __half* H116 = hb + HOFF_H116;
    __half* WF0h = hb + HOFF_WF0;
    __half* WF3h = hb + HOFF_WF3;
    __half* WF4h = hb + HOFF_WF4;
    __half* XPWh = hb + HOFF_XPW;
    __half* DTWh = hb + HOFF_DTW;
    __half* M2Wh = hb + HOFF_M2W;
    int* IDX = ib;
    int* INV = ib + MROWS;

    const int SM128 = NSTG*(128*PW + 128*PW)*4;   // 80KB
    const int SM64  = NSTG*(128*PW +  64*PW)*4;   // 60KB
    cudaFuncSetAttribute(k_mgemm<0,128>, cudaFuncAttributeMaxDynamicSharedMemorySize, SM128);
    cudaFuncSetAttribute(k_mgemm<1,64>,  cudaFuncAttributeMaxDynamicSharedMemorySize, SM64);
    cudaFuncSetAttribute(k_mgemm<2,128>, cudaFuncAttributeMaxDynamicSharedMemorySize, SM128);
    cudaFuncSetAttribute(k_mgemm<3,128>, cudaFuncAttributeMaxDynamicSharedMemorySize, SM128);
    cudaFuncSetAttribute(k_mgemm<4,128>, cudaFuncAttributeMaxDynamicSharedMemorySize, SM128);
    cudaFuncSetAttribute(k_mgemm<5,128>, cudaFuncAttributeMaxDynamicSharedMemorySize, SM128);

    // 1: x row stats (= gray) + fp16 copy of x
    k_rowstats<256,true><<<MROWS/8, 256>>>(x, MEAN, RSTD, X16);
    // 2: all weight prep + inits
    k_prep<<<864, 256>>>(in_w, norm1_g, norm1_b, in_b,
                         outp_w, outn_g, outn_b, outp_b,
                         mlp_w1, norm2_g, norm2_b, mlp_b1,
                         x_proj_w, dt_w, mlp_w2);
    // 3: fused grad + prio + sort
    k_sortfused<<<NB, 1024>>>(MEAN, fusion_w, prio_s, prio_o, GP, IDX, INV);
    // 4: in_proj GEMM  (profiling slot)
    k_mgemm<0,128><<<dim3(4,256), 256, SM128>>>(X16, 256, 256, WF0h, MEAN, RSTD, S0, U0,
        nullptr, XP16, 512, nullptr, nullptr, nullptr, nullptr, nullptr);
    // 5
    k_cpe<<<dim3(64, NB), 256>>>(XP16, cpe_w, cpe_b, INV, U16);
    // 6
    k_mgemm<1,64><<<dim3(1,256), 256, SM64>>>(U16, 512, 512, XPWh, nullptr, nullptr, ZV, ZV,
        XDBL, XD16, 64, GP, gC_w, gC_b, gC_wt, nullptr);
    // 7
    k_mgemm<2,128><<<dim3(4,256), 256, SM128>>>(XD16, 64, 32, DTWh, nullptr, nullptr, ZV, dt_b,
        DELTA, nullptr, 512, nullptr, nullptr, nullptr, nullptr, nullptr);
    // 8: scan (8 d/warp layout)
    k_scan<<<256, 64>>>(U16, DELTA, XDBL, A_logs, Ds, Y16);
    // 9
    k_rowstats_h<512><<<MROWS/8, 256>>>(Y16, MEAN, RSTD);
    // 10: out_proj + scatter + x residual -> X116 (fp16 only)
    k_mgemm<3,128><<<dim3(2,256), 256, SM128>>>(Y16, 512, 512, WF3h, MEAN, RSTD, S3, U3,
        nullptr, X116, 256, x, nullptr, nullptr, nullptr, IDX);
    // 11: X1 row stats from fp16
    k_rowstats_h<256><<<MROWS/8, 256>>>(X116, MEAN, RSTD);
    // 12
    k_mgemm<4,128><<<dim3(4,256), 256, SM128>>>(X116, 256, 256, WF4h, MEAN, RSTD, S4, U4,
        nullptr, H116, 512, nullptr, nullptr, nullptr, nullptr, nullptr);
    // 13: mlp2 + bias + X116 residual (fp16 via C16) -> out fp32
    k_mgemm<5,128><<<dim3(2,256), 256, SM128>>>(H116, 512, 512, M2Wh, nullptr, nullptr, ZV, mlp_b2,
        out, X116, 256, nullptr, nullptr, nullptr, nullptr, nullptr);
}

// round 16
// speedup vs baseline: 1.1367x; 1.1367x over previous
#include <cuda_runtime.h>
#include <cuda_fp16.h>
#include <math.h>

#define NB    8
#define NTOK  4096
#define DIMC  256
#define HIDC  512
#define MROWS (NB*NTOK)   // 32768

// ---------------- fp32 scratch ----------------
#define OFF_GP    0
#define OFF_MEAN  (OFF_GP   + MROWS)
#define OFF_RSTD  (OFF_MEAN + MROWS)
#define OFF_XDBL  (OFF_RSTD + MROWS)            // [MROWS,64]
#define OFF_DELTA (OFF_XDBL + MROWS*64)         // [MROWS,512]
#define OFF_S0    (OFF_DELTA+ MROWS*HIDC)
#define OFF_U0    (OFF_S0   + 512)
#define OFF_S3    (OFF_U0   + 512)
#define OFF_U3    (OFF_S3   + 256)
#define OFF_S4    (OFF_U3   + 256)
#define OFF_U4    (OFF_S4   + 512)
#define OFF_ZERO  (OFF_U4   + 512)
#define FTOTAL    (OFF_ZERO + 512)

__device__ __align__(16) float g_fbuf[FTOTAL];

// ---------------- fp16 scratch ----------------
#define HOFF_X16  0                              // [MROWS,256]
#define HOFF_XP16 (HOFF_X16 + MROWS*DIMC)        // [MROWS,512]
#define HOFF_U16  (HOFF_XP16+ MROWS*HIDC)        // [MROWS,512]
#define HOFF_XD16 (HOFF_U16 + MROWS*HIDC)        // [MROWS,64]
#define HOFF_Y16  (HOFF_XD16+ MROWS*64)          // [MROWS,512]
#define HOFF_X116 (HOFF_Y16 + MROWS*HIDC)        // [MROWS,256]
#define HOFF_H116 (HOFF_X116+ MROWS*DIMC)        // [MROWS,512]
#define HOFF_WF0  (HOFF_H116+ MROWS*HIDC)        // [512,256]
#define HOFF_WF3  (HOFF_WF0 + 512*256)           // [256,512]
#define HOFF_WF4  (HOFF_WF3 + 256*512)           // [512,256]
#define HOFF_XPW  (HOFF_WF4 + 512*256)           // [64,512]
#define HOFF_DTW  (HOFF_XPW + 64*512)            // [512,32]
#define HOFF_M2W  (HOFF_DTW + 512*32)            // [256,512]
#define HTOTAL    (HOFF_M2W + 256*512)

__device__ __align__(16) __half g_hbuf[HTOTAL];
__device__ int g_ibuf[2*MROWS + 32];             // idx, inv

// ================= PTX helpers =================
__device__ __forceinline__ void cpa16(unsigned s, const void* g){
    asm volatile("cp.async.cg.shared.global [%0], [%1], 16;" :: "r"(s), "l"(g));
}
#define CP_COMMIT() asm volatile("cp.async.commit_group;" ::: "memory")
#define CP_WAIT2()  asm volatile("cp.async.wait_group 2;" ::: "memory")
__device__ __forceinline__ unsigned smem_u32(const void* p){
    unsigned a;
    asm("{ .reg .u64 t; cvta.to.shared.u64 t, %1; cvt.u32.u64 %0, t; }" : "=r"(a) : "l"(p));
    return a;
}
__device__ __forceinline__ void mma16(float* c, const unsigned* a, const unsigned* b){
    asm volatile("mma.sync.aligned.m16n8k16.row.col.f32.f16.f16.f32 "
        "{%0,%1,%2,%3}, {%4,%5,%6,%7}, {%8,%9}, {%0,%1,%2,%3};"
        : "+f"(c[0]),"+f"(c[1]),"+f"(c[2]),"+f"(c[3])
        : "r"(a[0]),"r"(a[1]),"r"(a[2]),"r"(a[3]), "r"(b[0]),"r"(b[1]));
}
__device__ __forceinline__ void ldsm4(unsigned* r, unsigned addr){
    asm volatile("ldmatrix.sync.aligned.m8n8.x4.shared.b16 {%0,%1,%2,%3}, [%4];"
        : "=r"(r[0]),"=r"(r[1]),"=r"(r[2]),"=r"(r[3]) : "r"(addr));
}

// ---------------- merged prep: LN-fold x3, weight cvt x3, init ----------------
__device__ __forceinline__ void foldw(const float* __restrict__ W, const float* __restrict__ g,
                                      const float* __restrict__ b, const float* __restrict__ bias,
                                      __half* __restrict__ Wf, float* __restrict__ sv,
                                      float* __restrict__ uv, int n, int K, int lane){
    float s = 0.f, t = 0.f;
    for (int c=lane; c<K; c+=32){
        float w = W[(size_t)n*K + c];
        __half wh = __float2half_rn(w * g[c]);
        Wf[(size_t)n*K + c] = wh;
        s += __half2float(wh);
        t += w * b[c];
    }
    #pragma unroll
    for (int o=16;o>0;o>>=1){
        s += __shfl_down_sync(0xffffffffu, s, o);
        t += __shfl_down_sync(0xffffffffu, t, o);
    }
    if (lane == 0){ sv[n] = s; uv[n] = t + bias[n]; }
}

__global__ void k_prep(
    const float* in_w, const float* n1g, const float* n1b, const float* in_b,
    const float* outp_w, const float* ong, const float* onb, const float* outp_b,
    const float* mlp_w1, const float* n2g, const float* n2b, const float* mlp_b1,
    const float* x_proj_w, const float* dt_w, const float* mlp_w2)
{
    __half* hb = g_hbuf;
    float*  fb = g_fbuf;
    int blk = blockIdx.x, tid = threadIdx.x;
    int warp = tid >> 5, lane = tid & 31;
    if (blk == 0) fb[OFF_ZERO + tid] = 0.f;
    if (blk == 1) fb[OFF_ZERO + 256 + tid] = 0.f;

    if (blk < 64){
        foldw(in_w, n1g, n1b, in_b, hb+HOFF_WF0, fb+OFF_S0, fb+OFF_U0, blk*8+warp, 256, lane);
    } else if (blk < 96){
        foldw(outp_w, ong, onb, outp_b, hb+HOFF_WF3, fb+OFF_S3, fb+OFF_U3, (blk-64)*8+warp, 512, lane);
    } else if (blk < 160){
        foldw(mlp_w1, n2g, n2b, mlp_b1, hb+HOFF_WF4, fb+OFF_S4, fb+OFF_U4, (blk-96)*8+warp, 256, lane);
    } else {
        int t = (blk-160)*256 + tid;
        if (t < 32768)       hb[HOFF_XPW + t] = __float2half_rn(x_proj_w[t]);
        else if (t < 49152)  hb[HOFF_DTW + t - 32768] = __float2half_rn(dt_w[t - 32768]);
        else                 hb[HOFF_M2W + t - 49152] = __float2half_rn(mlp_w2[t - 49152]);
    }
}

// row stats (fp32 in); optionally writes fp16 copy
template<int KW, bool WRH>
__global__ void k_rowstats(const float* __restrict__ A, float* __restrict__ mean,
                           float* __restrict__ rstd, __half* __restrict__ o16){
    int row  = blockIdx.x*8 + (threadIdx.x >> 5);
    int lane = threadIdx.x & 31;
    const float4* p = (const float4*)(A + (size_t)row*KW);
    float s = 0.f, q = 0.f;
    #pragma unroll
    for (int c=lane; c<KW/4; c+=32){
        float4 v = p[c];
        s += v.x+v.y+v.z+v.w;
        q += v.x*v.x + v.y*v.y + v.z*v.z + v.w*v.w;
        if (WRH){
            *(__half2*)(o16 + (size_t)row*KW + 4*c)     = __floats2half2_rn(v.x, v.y);
            *(__half2*)(o16 + (size_t)row*KW + 4*c + 2) = __floats2half2_rn(v.z, v.w);
        }
    }
    #pragma unroll
    for (int o=16;o>0;o>>=1){
        s += __shfl_down_sync(0xffffffffu, s, o);
        q += __shfl_down_sync(0xffffffffu, q, o);
    }
    if (lane == 0){
        float m = s*(1.f/KW);
        float v = q*(1.f/KW) - m*m;
        mean[row] = m;
        rstd[row] = rsqrtf(v + 1e-5f);
    }
}

// row stats over fp16 rows
template<int KW>
__global__ void k_rowstats_h(const __half* __restrict__ A, float* __restrict__ mean,
                             float* __restrict__ rstd){
    int row  = blockIdx.x*8 + (threadIdx.x >> 5);
    int lane = threadIdx.x & 31;
    const __half2* p = (const __half2*)(A + (size_t)row*KW);
    float s = 0.f, q = 0.f;
    #pragma unroll
    for (int c=lane; c<KW/2; c+=32){
        float2 v = __half22float2(p[c]);
        s += v.x + v.y;
        q += v.x*v.x + v.y*v.y;
    }
    #pragma unroll
    for (int o=16;o>0;o>>=1){
        s += __shfl_down_sync(0xffffffffu, s, o);
        q += __shfl_down_sync(0xffffffffu, q, o);
    }
    if (lane == 0){
        float m = s*(1.f/KW);
        float v = q*(1.f/KW) - m*m;
        mean[row] = m;
        rstd[row] = rsqrtf(v + 1e-5f);
    }
}

// ---- fused: gradient magnitude + min/max + priority + stable bitonic argsort ----
__global__ void __launch_bounds__(1024) k_sortfused(
    const float* __restrict__ mean, const float* __restrict__ fw,
    const float* __restrict__ ps, const float* __restrict__ po,
    float* __restrict__ gp, int* __restrict__ idx, int* __restrict__ inv)
{
    __shared__ float s1[NTOK];
    __shared__ int   sv[NTOK];
    __shared__ float rmn[32], rmx[32];
    int b = blockIdx.x, tid = threadIdx.x;
    int warp = tid >> 5, lane = tid & 31;

    for (int i=tid; i<NTOK; i+=1024) s1[i] = mean[b*NTOK + i];
    float w0 = fw[0], w1 = fw[1], w2 = fw[2];
    float kk[9];
    kk[0] = -w0 - w1;        kk[1] = -2.f*w1 - w2;  kk[2] =  w0 - w1;
    kk[3] = -2.f*w0 - w2;    kk[4] =  4.f*w2;       kk[5] =  2.f*w0 - w2;
    kk[6] = -w0 + w1;        kk[7] =  2.f*w1 - w2;  kk[8] =  w0 + w1;
    __syncthreads();

    float gv[4];
    float mymin = 1e30f, mymax = 0.f;
    #pragma unroll
    for (int t=0;t<4;t++){
        int pix = tid + t*1024;
        int h = pix >> 6, w = pix & 63;
        float acc = 0.f;
        #pragma unroll
        for (int dh=-1; dh<=1; dh++)
            #pragma unroll
            for (int dw=-1; dw<=1; dw++){
                int hh = h+dh, ww = w+dw;
                float v = (hh>=0 && hh<64 && ww>=0 && ww<64) ? s1[hh*64+ww] : 0.f;
                acc += v * kk[(dh+1)*3 + (dw+1)];
            }
        float g = fabsf(acc);
        gv[t] = g;
        mymin = fminf(mymin, g); mymax = fmaxf(mymax, g);
    }
    #pragma unroll
    for (int o=16;o>0;o>>=1){
        mymin = fminf(mymin, __shfl_down_sync(0xffffffffu, mymin, o));
        mymax = fmaxf(mymax, __shfl_down_sync(0xffffffffu, mymax, o));
    }
    if (lane == 0){ rmn[warp] = mymin; rmx[warp] = mymax; }
    __syncthreads();
    if (tid < 32){
        float a = rmn[tid], c = rmx[tid];
        #pragma unroll
        for (int o=16;o>0;o>>=1){
            a = fminf(a, __shfl_down_sync(0xffffffffu, a, o));
            c = fmaxf(c, __shfl_down_sync(0xffffffffu, c, o));
        }
        if (tid == 0){ rmn[0] = a; rmx[0] = c; }
    }
    __syncthreads();
    float mn = rmn[0], mx = rmx[0];
    float psv = ps[0], pov = po[0];
    __syncthreads();
    #pragma unroll
    for (int t=0;t<4;t++){
        int pix = tid + t*1024;
        float tt = (gv[t]-mn) / (mx-mn+1e-8f);
        float z  = psv*tt + pov;
        float g  = 1.f/(1.f+expf(-z));
        gp[b*NTOK + pix] = g;
        s1[pix] = g; sv[pix] = pix;
    }
    for (int ksz=2; ksz<=NTOK; ksz<<=1){
        for (int j=ksz>>1; j>0; j>>=1){
            __syncthreads();
            #pragma unroll
            for (int base=0; base<NTOK; base+=1024){
                int i = base + tid;
                int ix = i ^ j;
                if (ix > i){
                    bool up = ((i & ksz) == 0);
                    float a = s1[i], c = s1[ix]; int va = sv[i], vc = sv[ix];
                    bool gt = (a > c) || (a == c && va > vc);
                    if (gt == up){ s1[i]=c; s1[ix]=a; sv[i]=vc; sv[ix]=va; }
                }
            }
        }
    }
    __syncthreads();
    for (int i=tid; i<NTOK; i+=1024){
        idx[b*NTOK + i]     = sv[i];
        inv[b*NTOK + sv[i]] = i;
    }
}

// ---- depthwise 3x3 CPE + sigmoid gate + permutation scatter into u16 ----
__global__ void __launch_bounds__(256) k_cpe(
    const __half* __restrict__ xp, const float* __restrict__ cw,
    const float* __restrict__ cb, const int* __restrict__ inv,
    __half* __restrict__ uo16)
{
    int h  = blockIdx.x;
    int b  = blockIdx.y;
    int ch = threadIdx.x * 2;
    float2 w[9];
    #pragma unroll
    for (int j=0;j<9;j++){ w[j].x = cw[ch*9+j]; w[j].y = cw[(ch+1)*9+j]; }
    float2 bv; bv.x = cb[ch]; bv.y = cb[ch+1];

    const __half* xpB = xp + ((size_t)b*NTOK)*HIDC + ch;
    __half* uoHB = uo16 + ((size_t)b*NTOK)*HIDC + ch;
    const int* invB = inv + b*NTOK + h*64;

    bool hm_ok = (h > 0), hp_ok = (h < 63);
    float2 zero = make_float2(0.f, 0.f);
    float2 cL[3], cM[3], cR[3];
    cL[0]=cL[1]=cL[2]=zero;
    cM[0] = hm_ok ? __half22float2(*(const __half2*)(xpB + (size_t)((h-1)*64)*HIDC)) : zero;
    cM[1] = __half22float2(*(const __half2*)(xpB + (size_t)(h*64)*HIDC));
    cM[2] = hp_ok ? __half22float2(*(const __half2*)(xpB + (size_t)((h+1)*64)*HIDC)) : zero;

    for (int ww=0; ww<64; ww++){
        if (ww < 63){
            cR[0] = hm_ok ? __half22float2(*(const __half2*)(xpB + (size_t)((h-1)*64+ww+1)*HIDC)) : zero;
            cR[1] = __half22float2(*(const __half2*)(xpB + (size_t)(h*64+ww+1)*HIDC));
            cR[2] = hp_ok ? __half22float2(*(const __half2*)(xpB + (size_t)((h+1)*64+ww+1)*HIDC)) : zero;
        } else { cR[0]=cR[1]=cR[2]=zero; }
        float ax = bv.x, ay = bv.y;
        #pragma unroll
        for (int r=0;r<3;r++){
            ax = fmaf(cL[r].x, w[r*3+0].x, ax);
            ay = fmaf(cL[r].y, w[r*3+0].y, ay);
            ax = fmaf(cM[r].x, w[r*3+1].x, ax);
            ay = fmaf(cM[r].y, w[r*3+1].y, ay);
            ax = fmaf(cR[r].x, w[r*3+2].x, ax);
            ay = fmaf(cR[r].y, w[r*3+2].y, ay);
        }
        float gx = 1.f/(1.f+__expf(-ax));
        float gy = 1.f/(1.f+__expf(-ay));
        int l = invB[ww];
        *(__half2*)(uoHB + (size_t)l*HIDC) = __floats2half2_rn(cM[1].x*gx, cM[1].y*gy);
        cL[0]=cM[0]; cL[1]=cM[1]; cL[2]=cM[2];
        cM[0]=cR[0]; cM[1]=cR[1]; cM[2]=cR[2];
    }
}

// ===== fp16 mma.sync GEMM: 256 thr / 8 warps (4x2), warp 32x64, K-chunk 32, 4-stage =====
// MODE 0: LN-folded +u -> f16 only   MODE 1: x_proj + Cm adjust (f32 + f16 copy)
// MODE 2: softplus(acc+u) (f32)      MODE 3: LN-folded, scatter + x -> f16 only
// MODE 4: LN-folded silu (f16 only)  MODE 5: acc+u+X116(f16 via C16) -> out (f32)
#define PW 20   // smem pitch in 32-bit words (40 fp16) -- stride 5 units mod 8 distinct
#define NSTG 4
template<int MODE, int NT>
__global__ void __launch_bounds__(256, 2) k_mgemm(
    const __half* __restrict__ A, int lda, int K,
    const __half* __restrict__ W,
    const float* __restrict__ rowm, const float* __restrict__ rowr,
    const float* __restrict__ svec, const float* __restrict__ uvec,
    float* __restrict__ C, __half* __restrict__ C16, int ldc,
    const float* __restrict__ aux0, const float* __restrict__ aux1,
    const float* __restrict__ aux2, const float* __restrict__ aux3,
    const int* __restrict__ ei)
{
    constexpr bool LNA  = (MODE==0 || MODE==3 || MODE==4);
    constexpr int NTILE = NT/16;
    constexpr int AW = 128*PW;
    constexpr int BW = NT*PW;
    extern __shared__ unsigned smemb[];
    unsigned sAu = smem_u32(smemb);
    unsigned sBu = sAu + NSTG*AW*4;

    int tid = threadIdx.x, lane = tid & 31, wid = tid >> 5;
    int warpM = wid & 3, warpN = wid >> 2;
    int mBase = blockIdx.y << 7;
    int nBase = blockIdx.x * NT;
    int Kt = K >> 5;
    int rA = lane >> 2, cA = lane & 3;

    float c[2][NTILE][4];
    #pragma unroll
    for (int i=0;i<2;i++)
        #pragma unroll
        for (int j=0;j<NTILE;j++)
            #pragma unroll
            for (int q=0;q<4;q++) c[i][j][q] = 0.f;

    auto ldStage = [&](int s, int k0){
        unsigned bA = sAu + s*(AW*4);
        #pragma unroll
        for (int i=tid; i<512; i+=256){
            int r = i>>2, hf = i&3;
            cpa16(bA + (r*PW + hf*4)*4, A + (size_t)(mBase+r)*lda + k0 + hf*8);
        }
        unsigned bB = sBu + s*(BW*4);
        #pragma unroll
        for (int i=tid; i<NT*4; i+=256){
            int r = i>>2, hf = i&3;
            cpa16(bB + (r*PW + hf*4)*4, W + (size_t)(nBase+r)*K + k0 + hf*8);
        }
    };

    int g8 = lane >> 3, r8 = lane & 7;
    unsigned offA[2], offB[NTILE/2];
    #pragma unroll
    for (int mt=0; mt<2; mt++){
        int row = warpM*32 + mt*16 + (g8 & 1)*8 + r8;
        offA[mt] = (unsigned)((row*PW + (g8>>1)*4)*4);
    }
    #pragma unroll
    for (int np=0; np<NTILE/2; np++){
        int row = warpN*(NT/2) + np*16 + (g8>>1)*8 + r8;
        offB[np] = (unsigned)((row*PW + (g8&1)*4)*4);
    }

    #pragma unroll
    for (int s=0; s<NSTG-1; s++){
        if (s < Kt) ldStage(s, s<<5);
        CP_COMMIT();
    }

    for (int k=0; k<Kt; k++){
        CP_WAIT2();
        __syncthreads();
        int t = k + NSTG - 1;
        if (t < Kt) ldStage(t & (NSTG-1), t<<5);
        CP_COMMIT();

        unsigned paB = sAu + (k & (NSTG-1))*(AW*4);
        unsigned pbB = sBu + (k & (NSTG-1))*(BW*4);
        #pragma unroll
        for (int kk=0; kk<2; kk++){
            unsigned koff = kk*32;
            unsigned af[2][4], bf[NTILE][2];
            ldsm4(af[0], paB + offA[0] + koff);
            ldsm4(af[1], paB + offA[1] + koff);
            #pragma unroll
            for (int np=0; np<NTILE/2; np++){
                unsigned tb[4];
                ldsm4(tb, pbB + offB[np] + koff);
                bf[2*np  ][0] = tb[0]; bf[2*np  ][1] = tb[1];
                bf[2*np+1][0] = tb[2]; bf[2*np+1][1] = tb[3];
            }
            #pragma unroll
            for (int mt=0; mt<2; mt++)
                #pragma unroll
                for (int nt=0; nt<NTILE; nt++)
                    mma16(c[mt][nt], af[mt], bf[nt]);
        }
    }

    // ---------------- epilogue ----------------
    float gcw = 0.f;
    if constexpr (MODE==1) gcw = aux3[0];

    #pragma unroll
    for (int mt=0; mt<2; mt++){
        #pragma unroll
        for (int half=0; half<2; half++){
            int m = mBase + warpM*32 + mt*16 + half*8 + rA;
            float mu = 0.f, rs = 0.f;
            if (LNA){ mu = rowm[m]; rs = rowr[m]; }
            float murs = mu*rs;
            int l = m & 4095, bb = m >> 12;
            int dest = m;
            if constexpr (MODE==3) dest = (m & ~4095) + ei[m];
            #pragma unroll
            for (int nt=0; nt<NTILE; nt++){
                int n0 = nBase + warpN*(NT/2) + nt*8 + (cA<<1);
                float vv[2] = { c[mt][nt][half*2], c[mt][nt][half*2+1] };
                float2 o;
                float* ov = (float*)&o;
                #pragma unroll
                for (int q=0; q<2; q++){
                    int n = n0 + q;
                    float acc = vv[q];
                    float v;
                    if (LNA) v = fmaf(rs, acc, fmaf(-murs, svec[n], uvec[n]));
                    else     v = acc + uvec[n];
                    if constexpr (MODE==1){
                        if (n >= 48){
                            int sidx = n - 48;
                            v += gcw * (aux0[bb*4096 + sidx*256 + (l>>4)] * aux1[l&15] + aux2[l&15]);
                        }
                    } else if constexpr (MODE==2){
                        v = fmaxf(v, 0.f) + log1pf(expf(-fabsf(v)));
                    } else if constexpr (MODE==4){
                        v = v / (1.f + expf(-v));
                    }
                    ov[q] = v;
                }
                if constexpr (MODE==3){
                    float2 xr = *(const float2*)(aux0 + (size_t)dest*ldc + n0);
                    o.x += xr.x; o.y += xr.y;
                    *(__half2*)(C16 + (size_t)dest*ldc + n0) = __floats2half2_rn(o.x, o.y);
                } else if constexpr (MODE==5){
                    float2 xr = __half22float2(*(const __half2*)(C16 + (size_t)m*ldc + n0));
                    o.x += xr.x; o.y += xr.y;
                    *(float2*)(C + (size_t)m*ldc + n0) = o;
                } else if constexpr (MODE==4 || MODE==0){
                    *(__half2*)(C16 + (size_t)m*ldc + n0) = __floats2half2_rn(o.x, o.y);
                } else if constexpr (MODE==1){
                    *(float2*)(C + (size_t)m*ldc + n0) = o;
                    *(__half2*)(C16 + (size_t)m*ldc + n0) = __floats2half2_rn(o.x, o.y);
                } else {
                    *(float2*)(C + (size_t)m*ldc + n0) = o;
                }
            }
        }
    }
}

// ---------------- selective scan ----------------
#define CHUNK 16
__global__ void __launch_bounds__(128, 2) k_scan(
    const __half* __restrict__ u16, const float* __restrict__ delta,
    const float* __restrict__ xdbl, const float* __restrict__ A_logs,
    const float* __restrict__ Ds, __half* __restrict__ y16)
{
    int lane = threadIdx.x & 31;
    int warp = threadIdx.x >> 5;
    int sl   = lane & 7;
    int blk  = blockIdx.x;
    int b    = blk >> 5;
    int sub  = blk & 31;
    int d    = sub*16 + warp*4 + (lane >> 3);
    float a0 = -expf(A_logs[d*16 + 2*sl]);
    float a1 = -expf(A_logs[d*16 + 2*sl + 1]);
    float dsd = Ds[d];
    size_t base = ((size_t)b*NTOK)*HIDC + d;
    size_t xb   = ((size_t)b*NTOK)*64 + 32 + 2*sl;
    float h0 = 0.f, h1 = 0.f;

    float  dl[2][CHUNK], uu[2][CHUNK];
    float2 Bv[2][CHUNK], Cv[2][CHUNK];

    #pragma unroll
    for (int j=0;j<CHUNK;j++){
        dl[0][j] = delta[base + (size_t)j*HIDC];
        uu[0][j] = __half2float(u16[base + (size_t)j*HIDC]);
        Bv[0][j] = *(const float2*)(xdbl + xb + (size_t)j*64);
        Cv[0][j] = *(const float2*)(xdbl + xb + (size_t)j*64 + 16);
    }
    #pragma unroll 2
    for (int c=0; c<NTOK/CHUNK; c++){
        int cur = c & 1, nxt = cur^1;
        if (c+1 < NTOK/CHUNK){
            int l1 = (c+1)*CHUNK;
            #pragma unroll
            for (int j=0;j<CHUNK;j++){
                dl[nxt][j] = delta[base + (size_t)(l1+j)*HIDC];
                uu[nxt][j] = __half2float(u16[base + (size_t)(l1+j)*HIDC]);
                Bv[nxt][j] = *(const float2*)(xdbl + xb + (size_t)(l1+j)*64);
                Cv[nxt][j] = *(const float2*)(xdbl + xb + (size_t)(l1+j)*64 + 16);
            }
        }
        #pragma unroll
        for (int j=0;j<CHUNK;j++){
            float dlt = dl[cur][j];
            float e0 = __expf(dlt*a0), e1 = __expf(dlt*a1);
            float du = dlt*uu[cur][j];
            h0 = fmaf(e0, h0, du*Bv[cur][j].x);
            h1 = fmaf(e1, h1, du*Bv[cur][j].y);
            float t = fmaf(h1, Cv[cur][j].y, h0*Cv[cur][j].x);
            t += __shfl_xor_sync(0xffffffffu, t, 1);
            t += __shfl_xor_sync(0xffffffffu, t, 2);
            t += __shfl_xor_sync(0xffffffffu, t, 4);
            if (sl == 0){
                float yv = fmaf(uu[cur][j], dsd, t);
                y16[base + (size_t)(c*CHUNK+j)*HIDC] = __float2half_rn(yv);
            }
        }
    }
}

// ---------------- host launcher ----------------
extern "C" void kernel_launch(void* const* d_in, const int* in_sizes, int n_in,
                              void* d_out, int out_size) {
    const float* x        = (const float*)d_in[0];
    const float* norm1_g  = (const float*)d_in[1];
    const float* norm1_b  = (const float*)d_in[2];
    const float* fusion_w = (const float*)d_in[3];
    const float* prio_s   = (const float*)d_in[4];
    const float* prio_o   = (const float*)d_in[5];
    const float* in_w     = (const float*)d_in[6];
    const float* in_b     = (const float*)d_in[7];
    const float* cpe_w    = (const float*)d_in[8];
    const float* cpe_b    = (const float*)d_in[9];
    const float* x_proj_w = (const float*)d_in[10];
    const float* dt_w     = (const float*)d_in[11];
    const float* dt_b     = (const float*)d_in[12];
    const float* A_logs   = (const float*)d_in[13];
    const float* Ds       = (const float*)d_in[14];
    const float* gC_w     = (const float*)d_in[15];
    const float* gC_b     = (const float*)d_in[16];
    const float* gC_wt    = (const float*)d_in[17];
    const float* outn_g   = (const float*)d_in[18];
    const float* outn_b   = (const float*)d_in[19];
    const float* outp_w   = (const float*)d_in[20];
    const float* outp_b   = (const float*)d_in[21];
    const float* norm2_g  = (const float*)d_in[22];
    const float* norm2_b  = (const float*)d_in[23];
    const float* mlp_w1   = (const float*)d_in[24];
    const float* mlp_b1   = (const float*)d_in[25];
    const float* mlp_w2   = (const float*)d_in[26];
    const float* mlp_b2   = (const float*)d_in[27];
    float* out = (float*)d_out;

    float*  fb; cudaGetSymbolAddress((void**)&fb, g_fbuf);
    __half* hb; cudaGetSymbolAddress((void**)&hb, g_hbuf);
    int*    ib; cudaGetSymbolAddress((void**)&ib, g_ibuf);
    float* GP    = fb + OFF_GP;
    float* MEAN  = fb + OFF_MEAN;
    float* RSTD  = fb + OFF_RSTD;
    float* XDBL  = fb + OFF_XDBL;
    float* DELTA = fb + OFF_DELTA;
    float* S0 = fb+OFF_S0; float* U0 = fb+OFF_U0;
    float* S3 = fb+OFF_S3; float* U3 = fb+OFF_U3;
    float* S4 = fb+OFF_S4; float* U4 = fb+OFF_U4;
    float* ZV = fb+OFF_ZERO;
    __half* X16  = hb + HOFF_X16;
    __half* XP16 = hb + HOFF_XP16;
    __half* U16  = hb + HOFF_U16;
    __half* XD16 = hb + HOFF_XD16;
    __half* Y16  = hb + HOFF_Y16;
    __half* X116 = hb + HOFF_X116;
    __half* H116 = hb + HOFF_H116;
    __half* WF0h = hb + HOFF_WF0;
    __half* WF3h = hb + HOFF_WF3;
    __half* WF4h = hb + HOFF_WF4;
    __half* XPWh = hb + HOFF_XPW;
    __half* DTWh = hb + HOFF_DTW;
    __half* M2Wh = hb + HOFF_M2W;
    int* IDX = ib;
    int* INV = ib + MROWS;

    const int SM128 = NSTG*(128*PW + 128*PW)*4;   // 80KB
    const int SM64  = NSTG*(128*PW +  64*PW)*4;   // 60KB
    cudaFuncSetAttribute(k_mgemm<0,128>, cudaFuncAttributeMaxDynamicSharedMemorySize, SM128);
    cudaFuncSetAttribute(k_mgemm<1,64>,  cudaFuncAttributeMaxDynamicSharedMemorySize, SM64);
    cudaFuncSetAttribute(k_mgemm<2,128>, cudaFuncAttributeMaxDynamicSharedMemorySize, SM128);
    cudaFuncSetAttribute(k_mgemm<3,128>, cudaFuncAttributeMaxDynamicSharedMemorySize, SM128);
    cudaFuncSetAttribute(k_mgemm<4,128>, cudaFuncAttributeMaxDynamicSharedMemorySize, SM128);
    cudaFuncSetAttribute(k_mgemm<5,128>, cudaFuncAttributeMaxDynamicSharedMemorySize, SM128);

    // 1: x row stats (= gray) + fp16 copy of x
    k_rowstats<256,true><<<MROWS/8, 256>>>(x, MEAN, RSTD, X16);
    // 2: all weight prep + inits
    k_prep<<<864, 256>>>(in_w, norm1_g, norm1_b, in_b,
                         outp_w, outn_g, outn_b, outp_b,
                         mlp_w1, norm2_g, norm2_b, mlp_b1,
                         x_proj_w, dt_w, mlp_w2);
    // 3: fused grad + prio + sort
    k_sortfused<<<NB, 1024>>>(MEAN, fusion_w, prio_s, prio_o, GP, IDX, INV);
    // 4: in_proj GEMM  (profiling slot)
    k_mgemm<0,128><<<dim3(4,256), 256, SM128>>>(X16, 256, 256, WF0h, MEAN, RSTD, S0, U0,
        nullptr, XP16, 512, nullptr, nullptr, nullptr, nullptr, nullptr);
    // 5
    k_cpe<<<dim3(64, NB), 256>>>(XP16, cpe_w, cpe_b, INV, U16);
    // 6
    k_mgemm<1,64><<<dim3(1,256), 256, SM64>>>(U16, 512, 512, XPWh, nullptr, nullptr, ZV, ZV,
        XDBL, XD16, 64, GP, gC_w, gC_b, gC_wt, nullptr);
    // 7
    k_mgemm<2,128><<<dim3(4,256), 256, SM128>>>(XD16, 64, 32, DTWh, nullptr, nullptr, ZV, dt_b,
        DELTA, nullptr, 512, nullptr, nullptr, nullptr, nullptr, nullptr);
    // 8
    k_scan<<<256, 128>>>(U16, DELTA, XDBL, A_logs, Ds, Y16);
    // 9
    k_rowstats_h<512><<<MROWS/8, 256>>>(Y16, MEAN, RSTD);
    // 10: out_proj + scatter + x residual -> X116 (fp16 only)
    k_mgemm<3,128><<<dim3(2,256), 256, SM128>>>(Y16, 512, 512, WF3h, MEAN, RSTD, S3, U3,
        nullptr, X116, 256, x, nullptr, nullptr, nullptr, IDX);
    // 11: X1 row stats from fp16
    k_rowstats_h<256><<<MROWS/8, 256>>>(X116, MEAN, RSTD);
    // 12
    k_mgemm<4,128><<<dim3(4,256), 256, SM128>>>(X116, 256, 256, WF4h, MEAN, RSTD, S4, U4,
        nullptr, H116, 512, nullptr, nullptr, nullptr, nullptr, nullptr);
    // 13: mlp2 + bias + X116 residual (fp16 via C16) -> out fp32
    k_mgemm<5,128><<<dim3(2,256), 256, SM128>>>(H116, 512, 512, M2Wh, nullptr, nullptr, ZV, mlp_b2,
        out, X116, 256, nullptr, nullptr, nullptr, nullptr, nullptr);
}

// round 17
// speedup vs baseline: 1.1833x; 1.0410x over previous
#include <cuda_runtime.h>
#include <cuda_fp16.h>
#include <math.h>

#define NB    8
#define NTOK  4096
#define DIMC  256
#define HIDC  512
#define MROWS (NB*NTOK)   // 32768

// ---------------- fp32 scratch ----------------
#define OFF_GP    0
#define OFF_MEAN  (OFF_GP   + MROWS)
#define OFF_RSTD  (OFF_MEAN + MROWS)
#define OFF_XDBL  (OFF_RSTD + MROWS)            // [MROWS,64]
#define OFF_S0    (OFF_XDBL + MROWS*64)
#define OFF_U0    (OFF_S0   + 512)
#define OFF_S3    (OFF_U0   + 512)
#define OFF_U3    (OFF_S3   + 256)
#define OFF_S4    (OFF_U3   + 256)
#define OFF_U4    (OFF_S4   + 512)
#define OFF_ZERO  (OFF_U4   + 512)
#define FTOTAL    (OFF_ZERO + 512)

__device__ __align__(16) float g_fbuf[FTOTAL];

// ---------------- fp16 scratch ----------------
#define HOFF_X16  0                              // [MROWS,256]
#define HOFF_XP16 (HOFF_X16 + MROWS*DIMC)        // [MROWS,512]
#define HOFF_U16  (HOFF_XP16+ MROWS*HIDC)        // [MROWS,512]
#define HOFF_XD16 (HOFF_U16 + MROWS*HIDC)        // [MROWS,64]
#define HOFF_D16  (HOFF_XD16+ MROWS*64)          // [MROWS,512] delta fp16
#define HOFF_Y16  (HOFF_D16 + MROWS*HIDC)        // [MROWS,512]
#define HOFF_X116 (HOFF_Y16 + MROWS*HIDC)        // [MROWS,256]
#define HOFF_H116 (HOFF_X116+ MROWS*DIMC)        // [MROWS,512]
#define HOFF_WF0  (HOFF_H116+ MROWS*HIDC)        // [512,256]
#define HOFF_WF3  (HOFF_WF0 + 512*256)           // [256,512]
#define HOFF_WF4  (HOFF_WF3 + 256*512)           // [512,256]
#define HOFF_XPW  (HOFF_WF4 + 512*256)           // [64,512]
#define HOFF_DTW  (HOFF_XPW + 64*512)            // [512,32]
#define HOFF_M2W  (HOFF_DTW + 512*32)            // [256,512]
#define HTOTAL    (HOFF_M2W + 256*512)

__device__ __align__(16) __half g_hbuf[HTOTAL];
__device__ int g_ibuf[2*MROWS + 32];             // idx, inv

// ================= PTX helpers =================
__device__ __forceinline__ void cpa16(unsigned s, const void* g){
    asm volatile("cp.async.cg.shared.global [%0], [%1], 16;" :: "r"(s), "l"(g));
}
#define CP_COMMIT() asm volatile("cp.async.commit_group;" ::: "memory")
#define CP_WAIT2()  asm volatile("cp.async.wait_group 2;" ::: "memory")
__device__ __forceinline__ unsigned smem_u32(const void* p){
    unsigned a;
    asm("{ .reg .u64 t; cvta.to.shared.u64 t, %1; cvt.u32.u64 %0, t; }" : "=r"(a) : "l"(p));
    return a;
}
__device__ __forceinline__ void mma16(float* c, const unsigned* a, const unsigned* b){
    asm volatile("mma.sync.aligned.m16n8k16.row.col.f32.f16.f16.f32 "
        "{%0,%1,%2,%3}, {%4,%5,%6,%7}, {%8,%9}, {%0,%1,%2,%3};"
        : "+f"(c[0]),"+f"(c[1]),"+f"(c[2]),"+f"(c[3])
        : "r"(a[0]),"r"(a[1]),"r"(a[2]),"r"(a[3]), "r"(b[0]),"r"(b[1]));
}
__device__ __forceinline__ void ldsm4(unsigned* r, unsigned addr){
    asm volatile("ldmatrix.sync.aligned.m8n8.x4.shared.b16 {%0,%1,%2,%3}, [%4];"
        : "=r"(r[0]),"=r"(r[1]),"=r"(r[2]),"=r"(r[3]) : "r"(addr));
}

// ---------------- merged prep: LN-fold x3, weight cvt x3, init ----------------
__device__ __forceinline__ void foldw(const float* __restrict__ W, const float* __restrict__ g,
                                      const float* __restrict__ b, const float* __restrict__ bias,
                                      __half* __restrict__ Wf, float* __restrict__ sv,
                                      float* __restrict__ uv, int n, int K, int lane){
    float s = 0.f, t = 0.f;
    for (int c=lane; c<K; c+=32){
        float w = W[(size_t)n*K + c];
        __half wh = __float2half_rn(w * g[c]);
        Wf[(size_t)n*K + c] = wh;
        s += __half2float(wh);
        t += w * b[c];
    }
    #pragma unroll
    for (int o=16;o>0;o>>=1){
        s += __shfl_down_sync(0xffffffffu, s, o);
        t += __shfl_down_sync(0xffffffffu, t, o);
    }
    if (lane == 0){ sv[n] = s; uv[n] = t + bias[n]; }
}

__global__ void k_prep(
    const float* in_w, const float* n1g, const float* n1b, const float* in_b,
    const float* outp_w, const float* ong, const float* onb, const float* outp_b,
    const float* mlp_w1, const float* n2g, const float* n2b, const float* mlp_b1,
    const float* x_proj_w, const float* dt_w, const float* mlp_w2)
{
    __half* hb = g_hbuf;
    float*  fb = g_fbuf;
    int blk = blockIdx.x, tid = threadIdx.x;
    int warp = tid >> 5, lane = tid & 31;
    if (blk == 0) fb[OFF_ZERO + tid] = 0.f;
    if (blk == 1) fb[OFF_ZERO + 256 + tid] = 0.f;

    if (blk < 64){
        foldw(in_w, n1g, n1b, in_b, hb+HOFF_WF0, fb+OFF_S0, fb+OFF_U0, blk*8+warp, 256, lane);
    } else if (blk < 96){
        foldw(outp_w, ong, onb, outp_b, hb+HOFF_WF3, fb+OFF_S3, fb+OFF_U3, (blk-64)*8+warp, 512, lane);
    } else if (blk < 160){
        foldw(mlp_w1, n2g, n2b, mlp_b1, hb+HOFF_WF4, fb+OFF_S4, fb+OFF_U4, (blk-96)*8+warp, 256, lane);
    } else {
        int t = (blk-160)*256 + tid;
        if (t < 32768)       hb[HOFF_XPW + t] = __float2half_rn(x_proj_w[t]);
        else if (t < 49152)  hb[HOFF_DTW + t - 32768] = __float2half_rn(dt_w[t - 32768]);
        else                 hb[HOFF_M2W + t - 49152] = __float2half_rn(mlp_w2[t - 49152]);
    }
}

// row stats (fp32 in); optionally writes fp16 copy
template<int KW, bool WRH>
__global__ void k_rowstats(const float* __restrict__ A, float* __restrict__ mean,
                           float* __restrict__ rstd, __half* __restrict__ o16){
    int row  = blockIdx.x*8 + (threadIdx.x >> 5);
    int lane = threadIdx.x & 31;
    const float4* p = (const float4*)(A + (size_t)row*KW);
    float s = 0.f, q = 0.f;
    #pragma unroll
    for (int c=lane; c<KW/4; c+=32){
        float4 v = p[c];
        s += v.x+v.y+v.z+v.w;
        q += v.x*v.x + v.y*v.y + v.z*v.z + v.w*v.w;
        if (WRH){
            *(__half2*)(o16 + (size_t)row*KW + 4*c)     = __floats2half2_rn(v.x, v.y);
            *(__half2*)(o16 + (size_t)row*KW + 4*c + 2) = __floats2half2_rn(v.z, v.w);
        }
    }
    #pragma unroll
    for (int o=16;o>0;o>>=1){
        s += __shfl_down_sync(0xffffffffu, s, o);
        q += __shfl_down_sync(0xffffffffu, q, o);
    }
    if (lane == 0){
        float m = s*(1.f/KW);
        float v = q*(1.f/KW) - m*m;
        mean[row] = m;
        rstd[row] = rsqrtf(v + 1e-5f);
    }
}

// row stats over fp16 rows
template<int KW>
__global__ void k_rowstats_h(const __half* __restrict__ A, float* __restrict__ mean,
                             float* __restrict__ rstd){
    int row  = blockIdx.x*8 + (threadIdx.x >> 5);
    int lane = threadIdx.x & 31;
    const __half2* p = (const __half2*)(A + (size_t)row*KW);
    float s = 0.f, q = 0.f;
    #pragma unroll
    for (int c=lane; c<KW/2; c+=32){
        float2 v = __half22float2(p[c]);
        s += v.x + v.y;
        q += v.x*v.x + v.y*v.y;
    }
    #pragma unroll
    for (int o=16;o>0;o>>=1){
        s += __shfl_down_sync(0xffffffffu, s, o);
        q += __shfl_down_sync(0xffffffffu, q, o);
    }
    if (lane == 0){
        float m = s*(1.f/KW);
        float v = q*(1.f/KW) - m*m;
        mean[row] = m;
        rstd[row] = rsqrtf(v + 1e-5f);
    }
}

// ---- fused: gradient magnitude + min/max + priority + stable bitonic argsort ----
__global__ void __launch_bounds__(1024) k_sortfused(
    const float* __restrict__ mean, const float* __restrict__ fw,
    const float* __restrict__ ps, const float* __restrict__ po,
    float* __restrict__ gp, int* __restrict__ idx, int* __restrict__ inv)
{
    __shared__ float s1[NTOK];
    __shared__ int   sv[NTOK];
    __shared__ float rmn[32], rmx[32];
    int b = blockIdx.x, tid = threadIdx.x;
    int warp = tid >> 5, lane = tid & 31;

    for (int i=tid; i<NTOK; i+=1024) s1[i] = mean[b*NTOK + i];
    float w0 = fw[0], w1 = fw[1], w2 = fw[2];
    float kk[9];
    kk[0] = -w0 - w1;        kk[1] = -2.f*w1 - w2;  kk[2] =  w0 - w1;
    kk[3] = -2.f*w0 - w2;    kk[4] =  4.f*w2;       kk[5] =  2.f*w0 - w2;
    kk[6] = -w0 + w1;        kk[7] =  2.f*w1 - w2;  kk[8] =  w0 + w1;
    __syncthreads();

    float gv[4];
    float mymin = 1e30f, mymax = 0.f;
    #pragma unroll
    for (int t=0;t<4;t++){
        int pix = tid + t*1024;
        int h = pix >> 6, w = pix & 63;
        float acc = 0.f;
        #pragma unroll
        for (int dh=-1; dh<=1; dh++)
            #pragma unroll
            for (int dw=-1; dw<=1; dw++){
                int hh = h+dh, ww = w+dw;
                float v = (hh>=0 && hh<64 && ww>=0 && ww<64) ? s1[hh*64+ww] : 0.f;
                acc += v * kk[(dh+1)*3 + (dw+1)];
            }
        float g = fabsf(acc);
        gv[t] = g;
        mymin = fminf(mymin, g); mymax = fmaxf(mymax, g);
    }
    #pragma unroll
    for (int o=16;o>0;o>>=1){
        mymin = fminf(mymin, __shfl_down_sync(0xffffffffu, mymin, o));
        mymax = fmaxf(mymax, __shfl_down_sync(0xffffffffu, mymax, o));
    }
    if (lane == 0){ rmn[warp] = mymin; rmx[warp] = mymax; }
    __syncthreads();
    if (tid < 32){
        float a = rmn[tid], c = rmx[tid];
        #pragma unroll
        for (int o=16;o>0;o>>=1){
            a = fminf(a, __shfl_down_sync(0xffffffffu, a, o));
            c = fmaxf(c, __shfl_down_sync(0xffffffffu, c, o));
        }
        if (tid == 0){ rmn[0] = a; rmx[0] = c; }
    }
    __syncthreads();
    float mn = rmn[0], mx = rmx[0];
    float psv = ps[0], pov = po[0];
    __syncthreads();
    #pragma unroll
    for (int t=0;t<4;t++){
        int pix = tid + t*1024;
        float tt = (gv[t]-mn) / (mx-mn+1e-8f);
        float z  = psv*tt + pov;
        float g  = 1.f/(1.f+expf(-z));
        gp[b*NTOK + pix] = g;
        s1[pix] = g; sv[pix] = pix;
    }
    for (int ksz=2; ksz<=NTOK; ksz<<=1){
        for (int j=ksz>>1; j>0; j>>=1){
            __syncthreads();
            #pragma unroll
            for (int base=0; base<NTOK; base+=1024){
                int i = base + tid;
                int ix = i ^ j;
                if (ix > i){
                    bool up = ((i & ksz) == 0);
                    float a = s1[i], c = s1[ix]; int va = sv[i], vc = sv[ix];
                    bool gt = (a > c) || (a == c && va > vc);
                    if (gt == up){ s1[i]=c; s1[ix]=a; sv[i]=vc; sv[ix]=va; }
                }
            }
        }
    }
    __syncthreads();
    for (int i=tid; i<NTOK; i+=1024){
        idx[b*NTOK + i]     = sv[i];
        inv[b*NTOK + sv[i]] = i;
    }
}

// ---- depthwise 3x3 CPE + sigmoid gate + permutation scatter into u16 ----
__global__ void __launch_bounds__(256) k_cpe(
    const __half* __restrict__ xp, const float* __restrict__ cw,
    const float* __restrict__ cb, const int* __restrict__ inv,
    __half* __restrict__ uo16)
{
    int h  = blockIdx.x;
    int b  = blockIdx.y;
    int ch = threadIdx.x * 2;
    float2 w[9];
    #pragma unroll
    for (int j=0;j<9;j++){ w[j].x = cw[ch*9+j]; w[j].y = cw[(ch+1)*9+j]; }
    float2 bv; bv.x = cb[ch]; bv.y = cb[ch+1];

    const __half* xpB = xp + ((size_t)b*NTOK)*HIDC + ch;
    __half* uoHB = uo16 + ((size_t)b*NTOK)*HIDC + ch;
    const int* invB = inv + b*NTOK + h*64;

    bool hm_ok = (h > 0), hp_ok = (h < 63);
    float2 zero = make_float2(0.f, 0.f);
    float2 cL[3], cM[3], cR[3];
    cL[0]=cL[1]=cL[2]=zero;
    cM[0] = hm_ok ? __half22float2(*(const __half2*)(xpB + (size_t)((h-1)*64)*HIDC)) : zero;
    cM[1] = __half22float2(*(const __half2*)(xpB + (size_t)(h*64)*HIDC));
    cM[2] = hp_ok ? __half22float2(*(const __half2*)(xpB + (size_t)((h+1)*64)*HIDC)) : zero;

    for (int ww=0; ww<64; ww++){
        if (ww < 63){
            cR[0] = hm_ok ? __half22float2(*(const __half2*)(xpB + (size_t)((h-1)*64+ww+1)*HIDC)) : zero;
            cR[1] = __half22float2(*(const __half2*)(xpB + (size_t)(h*64+ww+1)*HIDC));
            cR[2] = hp_ok ? __half22float2(*(const __half2*)(xpB + (size_t)((h+1)*64+ww+1)*HIDC)) : zero;
        } else { cR[0]=cR[1]=cR[2]=zero; }
        float ax = bv.x, ay = bv.y;
        #pragma unroll
        for (int r=0;r<3;r++){
            ax = fmaf(cL[r].x, w[r*3+0].x, ax);
            ay = fmaf(cL[r].y, w[r*3+0].y, ay);
            ax = fmaf(cM[r].x, w[r*3+1].x, ax);
            ay = fmaf(cM[r].y, w[r*3+1].y, ay);
            ax = fmaf(cR[r].x, w[r*3+2].x, ax);
            ay = fmaf(cR[r].y, w[r*3+2].y, ay);
        }
        float gx = 1.f/(1.f+__expf(-ax));
        float gy = 1.f/(1.f+__expf(-ay));
        int l = invB[ww];
        *(__half2*)(uoHB + (size_t)l*HIDC) = __floats2half2_rn(cM[1].x*gx, cM[1].y*gy);
        cL[0]=cM[0]; cL[1]=cM[1]; cL[2]=cM[2];
        cM[0]=cR[0]; cM[1]=cR[1]; cM[2]=cR[2];
    }
}

// ===== fp16 mma.sync GEMM: 256 thr / 8 warps (4x2), warp 32x64, K-chunk 32, 4-stage =====
// MODE 0: LN-folded +u -> f16 only   MODE 1: x_proj + Cm adjust (f32 + f16 copy)
// MODE 2: softplus(acc+u) -> f16     MODE 3: LN-folded, scatter + x -> f16 only
// MODE 4: LN-folded silu (f16 only)  MODE 5: acc+u+X116(f16 via C16) -> out (f32)
#define PW 20   // smem pitch in 32-bit words (40 fp16) -- stride 5 units mod 8 distinct
#define NSTG 4
template<int MODE, int NT>
__global__ void __launch_bounds__(256, 2) k_mgemm(
    const __half* __restrict__ A, int lda, int K,
    const __half* __restrict__ W,
    const float* __restrict__ rowm, const float* __restrict__ rowr,
    const float* __restrict__ svec, const float* __restrict__ uvec,
    float* __restrict__ C, __half* __restrict__ C16, int ldc,
    const float* __restrict__ aux0, const float* __restrict__ aux1,
    const float* __restrict__ aux2, const float* __restrict__ aux3,
    const int* __restrict__ ei)
{
    constexpr bool LNA  = (MODE==0 || MODE==3 || MODE==4);
    constexpr int NTILE = NT/16;
    constexpr int AW = 128*PW;
    constexpr int BW = NT*PW;
    extern __shared__ unsigned smemb[];
    unsigned sAu = smem_u32(smemb);
    unsigned sBu = sAu + NSTG*AW*4;

    int tid = threadIdx.x, lane = tid & 31, wid = tid >> 5;
    int warpM = wid & 3, warpN = wid >> 2;
    int mBase = blockIdx.y << 7;
    int nBase = blockIdx.x * NT;
    int Kt = K >> 5;
    int rA = lane >> 2, cA = lane & 3;

    float c[2][NTILE][4];
    #pragma unroll
    for (int i=0;i<2;i++)
        #pragma unroll
        for (int j=0;j<NTILE;j++)
            #pragma unroll
            for (int q=0;q<4;q++) c[i][j][q] = 0.f;

    auto ldStage = [&](int s, int k0){
        unsigned bA = sAu + s*(AW*4);
        #pragma unroll
        for (int i=tid; i<512; i+=256){
            int r = i>>2, hf = i&3;
            cpa16(bA + (r*PW + hf*4)*4, A + (size_t)(mBase+r)*lda + k0 + hf*8);
        }
        unsigned bB = sBu + s*(BW*4);
        #pragma unroll
        for (int i=tid; i<NT*4; i+=256){
            int r = i>>2, hf = i&3;
            cpa16(bB + (r*PW + hf*4)*4, W + (size_t)(nBase+r)*K + k0 + hf*8);
        }
    };

    int g8 = lane >> 3, r8 = lane & 7;
    unsigned offA[2], offB[NTILE/2];
    #pragma unroll
    for (int mt=0; mt<2; mt++){
        int row = warpM*32 + mt*16 + (g8 & 1)*8 + r8;
        offA[mt] = (unsigned)((row*PW + (g8>>1)*4)*4);
    }
    #pragma unroll
    for (int np=0; np<NTILE/2; np++){
        int row = warpN*(NT/2) + np*16 + (g8>>1)*8 + r8;
        offB[np] = (unsigned)((row*PW + (g8&1)*4)*4);
    }

    #pragma unroll
    for (int s=0; s<NSTG-1; s++){
        if (s < Kt) ldStage(s, s<<5);
        CP_COMMIT();
    }

    for (int k=0; k<Kt; k++){
        CP_WAIT2();
        __syncthreads();
        int t = k + NSTG - 1;
        if (t < Kt) ldStage(t & (NSTG-1), t<<5);
        CP_COMMIT();

        unsigned paB = sAu + (k & (NSTG-1))*(AW*4);
        unsigned pbB = sBu + (k & (NSTG-1))*(BW*4);
        #pragma unroll
        for (int kk=0; kk<2; kk++){
            unsigned koff = kk*32;
            unsigned af[2][4], bf[NTILE][2];
            ldsm4(af[0], paB + offA[0] + koff);
            ldsm4(af[1], paB + offA[1] + koff);
            #pragma unroll
            for (int np=0; np<NTILE/2; np++){
                unsigned tb[4];
                ldsm4(tb, pbB + offB[np] + koff);
                bf[2*np  ][0] = tb[0]; bf[2*np  ][1] = tb[1];
                bf[2*np+1][0] = tb[2]; bf[2*np+1][1] = tb[3];
            }
            #pragma unroll
            for (int mt=0; mt<2; mt++)
                #pragma unroll
                for (int nt=0; nt<NTILE; nt++)
                    mma16(c[mt][nt], af[mt], bf[nt]);
        }
    }

    // ---------------- epilogue ----------------
    float gcw = 0.f;
    if constexpr (MODE==1) gcw = aux3[0];

    #pragma unroll
    for (int mt=0; mt<2; mt++){
        #pragma unroll
        for (int half=0; half<2; half++){
            int m = mBase + warpM*32 + mt*16 + half*8 + rA;
            float mu = 0.f, rs = 0.f;
            if (LNA){ mu = rowm[m]; rs = rowr[m]; }
            float murs = mu*rs;
            int l = m & 4095, bb = m >> 12;
            int dest = m;
            if constexpr (MODE==3) dest = (m & ~4095) + ei[m];
            #pragma unroll
            for (int nt=0; nt<NTILE; nt++){
                int n0 = nBase + warpN*(NT/2) + nt*8 + (cA<<1);
                float vv[2] = { c[mt][nt][half*2], c[mt][nt][half*2+1] };
                float2 o;
                float* ov = (float*)&o;
                #pragma unroll
                for (int q=0; q<2; q++){
                    int n = n0 + q;
                    float acc = vv[q];
                    float v;
                    if (LNA) v = fmaf(rs, acc, fmaf(-murs, svec[n], uvec[n]));
                    else     v = acc + uvec[n];
                    if constexpr (MODE==1){
                        if (n >= 48){
                            int sidx = n - 48;
                            v += gcw * (aux0[bb*4096 + sidx*256 + (l>>4)] * aux1[l&15] + aux2[l&15]);
                        }
                    } else if constexpr (MODE==2){
                        v = fmaxf(v, 0.f) + log1pf(expf(-fabsf(v)));
                    } else if constexpr (MODE==4){
                        v = v / (1.f + expf(-v));
                    }
                    ov[q] = v;
                }
                if constexpr (MODE==3){
                    float2 xr = *(const float2*)(aux0 + (size_t)dest*ldc + n0);
                    o.x += xr.x; o.y += xr.y;
                    *(__half2*)(C16 + (size_t)dest*ldc + n0) = __floats2half2_rn(o.x, o.y);
                } else if constexpr (MODE==5){
                    float2 xr = __half22float2(*(const __half2*)(C16 + (size_t)m*ldc + n0));
                    o.x += xr.x; o.y += xr.y;
                    *(float2*)(C + (size_t)m*ldc + n0) = o;
                } else if constexpr (MODE==4 || MODE==0 || MODE==2){
                    *(__half2*)(C16 + (size_t)m*ldc + n0) = __floats2half2_rn(o.x, o.y);
                } else if constexpr (MODE==1){
                    *(float2*)(C + (size_t)m*ldc + n0) = o;
                    *(__half2*)(C16 + (size_t)m*ldc + n0) = __floats2half2_rn(o.x, o.y);
                } else {
                    *(float2*)(C + (size_t)m*ldc + n0) = o;
                }
            }
        }
    }
}

// ---------------- selective scan (delta fp16) ----------------
#define CHUNK 16
__global__ void __launch_bounds__(128, 2) k_scan(
    const __half* __restrict__ u16, const __half* __restrict__ d16,
    const float* __restrict__ xdbl, const float* __restrict__ A_logs,
    const float* __restrict__ Ds, __half* __restrict__ y16)
{
    int lane = threadIdx.x & 31;
    int warp = threadIdx.x >> 5;
    int sl   = lane & 7;
    int blk  = blockIdx.x;
    int b    = blk >> 5;
    int sub  = blk & 31;
    int d    = sub*16 + warp*4 + (lane >> 3);
    float a0 = -expf(A_logs[d*16 + 2*sl]);
    float a1 = -expf(A_logs[d*16 + 2*sl + 1]);
    float dsd = Ds[d];
    size_t base = ((size_t)b*NTOK)*HIDC + d;
    size_t xb   = ((size_t)b*NTOK)*64 + 32 + 2*sl;
    float h0 = 0.f, h1 = 0.f;

    float  dl[2][CHUNK], uu[2][CHUNK];
    float2 Bv[2][CHUNK], Cv[2][CHUNK];

    #pragma unroll
    for (int j=0;j<CHUNK;j++){
        dl[0][j] = __half2float(d16[base + (size_t)j*HIDC]);
        uu[0][j] = __half2float(u16[base + (size_t)j*HIDC]);
        Bv[0][j] = *(const float2*)(xdbl + xb + (size_t)j*64);
        Cv[0][j] = *(const float2*)(xdbl + xb + (size_t)j*64 + 16);
    }
    #pragma unroll 2
    for (int c=0; c<NTOK/CHUNK; c++){
        int cur = c & 1, nxt = cur^1;
        if (c+1 < NTOK/CHUNK){
            int l1 = (c+1)*CHUNK;
            #pragma unroll
            for (int j=0;j<CHUNK;j++){
                dl[nxt][j] = __half2float(d16[base + (size_t)(l1+j)*HIDC]);
                uu[nxt][j] = __half2float(u16[base + (size_t)(l1+j)*HIDC]);
                Bv[nxt][j] = *(const float2*)(xdbl + xb + (size_t)(l1+j)*64);
                Cv[nxt][j] = *(const float2*)(xdbl + xb + (size_t)(l1+j)*64 + 16);
            }
        }
        #pragma unroll
        for (int j=0;j<CHUNK;j++){
            float dlt = dl[cur][j];
            float e0 = __expf(dlt*a0), e1 = __expf(dlt*a1);
            float du = dlt*uu[cur][j];
            h0 = fmaf(e0, h0, du*Bv[cur][j].x);
            h1 = fmaf(e1, h1, du*Bv[cur][j].y);
            float t = fmaf(h1, Cv[cur][j].y, h0*Cv[cur][j].x);
            t += __shfl_xor_sync(0xffffffffu, t, 1);
            t += __shfl_xor_sync(0xffffffffu, t, 2);
            t += __shfl_xor_sync(0xffffffffu, t, 4);
            if (sl == 0){
                float yv = fmaf(uu[cur][j], dsd, t);
                y16[base + (size_t)(c*CHUNK+j)*HIDC] = __float2half_rn(yv);
            }
        }
    }
}

// ---------------- host launcher ----------------
extern "C" void kernel_launch(void* const* d_in, const int* in_sizes, int n_in,
                              void* d_out, int out_size) {
    const float* x        = (const float*)d_in[0];
    const float* norm1_g  = (const float*)d_in[1];
    const float* norm1_b  = (const float*)d_in[2];
    const float* fusion_w = (const float*)d_in[3];
    const float* prio_s   = (const float*)d_in[4];
    const float* prio_o   = (const float*)d_in[5];
    const float* in_w     = (const float*)d_in[6];
    const float* in_b     = (const float*)d_in[7];
    const float* cpe_w    = (const float*)d_in[8];
    const float* cpe_b    = (const float*)d_in[9];
    const float* x_proj_w = (const float*)d_in[10];
    const float* dt_w     = (const float*)d_in[11];
    const float* dt_b     = (const float*)d_in[12];
    const float* A_logs   = (const float*)d_in[13];
    const float* Ds       = (const float*)d_in[14];
    const float* gC_w     = (const float*)d_in[15];
    const float* gC_b     = (const float*)d_in[16];
    const float* gC_wt    = (const float*)d_in[17];
    const float* outn_g   = (const float*)d_in[18];
    const float* outn_b   = (const float*)d_in[19];
    const float* outp_w   = (const float*)d_in[20];
    const float* outp_b   = (const float*)d_in[21];
    const float* norm2_g  = (const float*)d_in[22];
    const float* norm2_b  = (const float*)d_in[23];
    const float* mlp_w1   = (const float*)d_in[24];
    const float* mlp_b1   = (const float*)d_in[25];
    const float* mlp_w2   = (const float*)d_in[26];
    const float* mlp_b2   = (const float*)d_in[27];
    float* out = (float*)d_out;

    float*  fb; cudaGetSymbolAddress((void**)&fb, g_fbuf);
    __half* hb; cudaGetSymbolAddress((void**)&hb, g_hbuf);
    int*    ib; cudaGetSymbolAddress((void**)&ib, g_ibuf);
    float* GP    = fb + OFF_GP;
    float* MEAN  = fb + OFF_MEAN;
    float* RSTD  = fb + OFF_RSTD;
    float* XDBL  = fb + OFF_XDBL;
    float* S0 = fb+OFF_S0; float* U0 = fb+OFF_U0;
    float* S3 = fb+OFF_S3; float* U3 = fb+OFF_U3;
    float* S4 = fb+OFF_S4; float* U4 = fb+OFF_U4;
    float* ZV = fb+OFF_ZERO;
    __half* X16  = hb + HOFF_X16;
    __half* XP16 = hb + HOFF_XP16;
    __half* U16  = hb + HOFF_U16;
    __half* XD16 = hb + HOFF_XD16;
    __half* D16  = hb + HOFF_D16;
    __half* Y16  = hb + HOFF_Y16;
    __half* X116 = hb + HOFF_X116;
    __half* H116 = hb + HOFF_H116;
    __half* WF0h = hb + HOFF_WF0;
    __half* WF3h = hb + HOFF_WF3;
    __half* WF4h = hb + HOFF_WF4;
    __half* XPWh = hb + HOFF_XPW;
    __half* DTWh = hb + HOFF_DTW;
    __half* M2Wh = hb + HOFF_M2W;
    int* IDX = ib;
    int* INV = ib + MROWS;

    const int SM128 = NSTG*(128*PW + 128*PW)*4;   // 80KB
    const int SM64  = NSTG*(128*PW +  64*PW)*4;   // 60KB
    cudaFuncSetAttribute(k_mgemm<0,128>, cudaFuncAttributeMaxDynamicSharedMemorySize, SM128);
    cudaFuncSetAttribute(k_mgemm<1,64>,  cudaFuncAttributeMaxDynamicSharedMemorySize, SM64);
    cudaFuncSetAttribute(k_mgemm<2,128>, cudaFuncAttributeMaxDynamicSharedMemorySize, SM128);
    cudaFuncSetAttribute(k_mgemm<3,128>, cudaFuncAttributeMaxDynamicSharedMemorySize, SM128);
    cudaFuncSetAttribute(k_mgemm<4,128>, cudaFuncAttributeMaxDynamicSharedMemorySize, SM128);
    cudaFuncSetAttribute(k_mgemm<5,128>, cudaFuncAttributeMaxDynamicSharedMemorySize, SM128);

    // 1: x row stats (= gray) + fp16 copy of x
    k_rowstats<256,true><<<MROWS/8, 256>>>(x, MEAN, RSTD, X16);
    // 2: all weight prep + inits
    k_prep<<<864, 256>>>(in_w, norm1_g, norm1_b, in_b,
                         outp_w, outn_g, outn_b, outp_b,
                         mlp_w1, norm2_g, norm2_b, mlp_b1,
                         x_proj_w, dt_w, mlp_w2);
    // 3: fused grad + prio + sort
    k_sortfused<<<NB, 1024>>>(MEAN, fusion_w, prio_s, prio_o, GP, IDX, INV);
    // 4: in_proj GEMM  (profiling slot)
    k_mgemm<0,128><<<dim3(4,256), 256, SM128>>>(X16, 256, 256, WF0h, MEAN, RSTD, S0, U0,
        nullptr, XP16, 512, nullptr, nullptr, nullptr, nullptr, nullptr);
    // 5
    k_cpe<<<dim3(64, NB), 256>>>(XP16, cpe_w, cpe_b, INV, U16);
    // 6
    k_mgemm<1,64><<<dim3(1,256), 256, SM64>>>(U16, 512, 512, XPWh, nullptr, nullptr, ZV, ZV,
        XDBL, XD16, 64, GP, gC_w, gC_b, gC_wt, nullptr);
    // 7: dt GEMM -> delta fp16
    k_mgemm<2,128><<<dim3(4,256), 256, SM128>>>(XD16, 64, 32, DTWh, nullptr, nullptr, ZV, dt_b,
        nullptr, D16, 512, nullptr, nullptr, nullptr, nullptr, nullptr);
    // 8
    k_scan<<<256, 128>>>(U16, D16, XDBL, A_logs, Ds, Y16);
    // 9
    k_rowstats_h<512><<<MROWS/8, 256>>>(Y16, MEAN, RSTD);
    // 10: out_proj + scatter + x residual -> X116 (fp16 only)
    k_mgemm<3,128><<<dim3(2,256), 256, SM128>>>(Y16, 512, 512, WF3h, MEAN, RSTD, S3, U3,
        nullptr, X116, 256, x, nullptr, nullptr, nullptr, IDX);
    // 11: X1 row stats from fp16
    k_rowstats_h<256><<<MROWS/8, 256>>>(X116, MEAN, RSTD);
    // 12
    k_mgemm<4,128><<<dim3(4,256), 256, SM128>>>(X116, 256, 256, WF4h, MEAN, RSTD, S4, U4,
        nullptr, H116, 512, nullptr, nullptr, nullptr, nullptr, nullptr);
    // 13: mlp2 + bias + X116 residual (fp16 via C16) -> out fp32
    k_mgemm<5,128><<<dim3(2,256), 256, SM128>>>(H116, 512, 512, M2Wh, nullptr, nullptr, ZV, mlp_b2,
        out, X116, 256, nullptr, nullptr, nullptr, nullptr, nullptr);
}